// round 14
// baseline (speedup 1.0000x reference)
#include <cuda_runtime.h>
#include <cuda_bf16.h>
#include <math.h>
#include <stdint.h>

// Problem constants
#define BB   128      // batch
#define TT   512      // time steps
#define HH   512      // hidden
#define II   128      // input dim
#define G4   2048     // 4*H

// ---------------- scratch (static device memory; no allocations) ----------
__device__ float g_pre [(size_t)BB * TT * G4];
__device__ __align__(16) __nv_bfloat16 g_bufXh[(size_t)BB * TT * HH];
__device__ __align__(16) __nv_bfloat16 g_bufXl[(size_t)BB * TT * HH];
__device__ __align__(16) __nv_bfloat16 g_bufYh[(size_t)BB * TT * HH];
__device__ __align__(16) __nv_bfloat16 g_bufYl[(size_t)BB * TT * HH];
__device__ __align__(16) __nv_bfloat16 g_xh[(size_t)BB * TT * II];
__device__ __align__(16) __nv_bfloat16 g_xl[(size_t)BB * TT * II];
// weight planes: [enc0 2048x128][enc1 2048x512][dec0 2048x128][dec1 2048x512][fc 128x512]
#define WO0 0
#define WO1 (WO0 + 2048 * 128)
#define WO2 (WO1 + 2048 * 512)
#define WO3 (WO2 + 2048 * 128)
#define WO4 (WO3 + 2048 * 512)
#define WTOT (WO4 + 128 * 512)
__device__ __align__(16) __nv_bfloat16 g_wh[WTOT];
__device__ __align__(16) __nv_bfloat16 g_wl[WTOT];
// slot barrier: 4 layers x 4 groups x 32 slots (one 128B line per group)
__device__ unsigned g_barrier[512];

// ---------------- tiny init kernels ----------------------------------------
__global__ void zero_bar(unsigned* p, int n) {
    int i = blockIdx.x * blockDim.x + threadIdx.x;
    if (i < n) p[i] = 0u;
}
__global__ void split_planes(const float* __restrict__ in,
                             __nv_bfloat16* __restrict__ oh,
                             __nv_bfloat16* __restrict__ ol, int n) {
    int i = blockIdx.x * blockDim.x + threadIdx.x;
    if (i < n) {
        float v = in[i];
        __nv_bfloat16 h = __float2bfloat16_rn(v);
        oh[i] = h;
        ol[i] = __float2bfloat16_rn(v - __bfloat162float(h));
    }
}

// ======================= helpers (compute_103-safe) ========================
__device__ __forceinline__ uint32_t smem_u32(const void* p) {
    return (uint32_t)__cvta_generic_to_shared(p);
}

#define LDSM4(d, addr)                                                        \
    asm volatile("ldmatrix.sync.aligned.m8n8.x4.shared.b16 "                  \
                 "{%0,%1,%2,%3}, [%4];"                                       \
                 : "=r"((d)[0]), "=r"((d)[1]), "=r"((d)[2]), "=r"((d)[3])     \
                 : "r"(addr))

#define MMA_BF16(cc, a, bb0, bb1)                                             \
    asm volatile("mma.sync.aligned.m16n8k16.row.col.f32.bf16.bf16.f32 "       \
                 "{%0,%1,%2,%3}, {%4,%5,%6,%7}, {%8,%9}, {%0,%1,%2,%3};"      \
                 : "+f"((cc)[0]), "+f"((cc)[1]), "+f"((cc)[2]), "+f"((cc)[3]) \
                 : "r"((a)[0]), "r"((a)[1]), "r"((a)[2]), "r"((a)[3]),        \
                   "r"(bb0), "r"(bb1))

#define CP_A16(dst, src, sz)                                                  \
    asm volatile("cp.async.cg.shared.global [%0], [%1], 16, %2;"              \
                 :: "r"(dst), "l"(src), "r"(sz) : "memory")
#define CP_COMMIT() asm volatile("cp.async.commit_group;" ::: "memory")
#define CP_WAIT1()  asm volatile("cp.async.wait_group 1;" ::: "memory")
#define CP_WAIT0()  asm volatile("cp.async.wait_group 0;" ::: "memory")

__device__ __forceinline__ void split2(float x, float y,
                                       uint32_t& hi, uint32_t& lo) {
    __nv_bfloat16 hx = __float2bfloat16_rn(x);
    __nv_bfloat16 hy = __float2bfloat16_rn(y);
    __nv_bfloat16 lx = __float2bfloat16_rn(x - __bfloat162float(hx));
    __nv_bfloat16 ly = __float2bfloat16_rn(y - __bfloat162float(hy));
    hi = ((uint32_t)__bfloat16_as_ushort(hy) << 16) | __bfloat16_as_ushort(hx);
    lo = ((uint32_t)__bfloat16_as_ushort(ly) << 16) | __bfloat16_as_ushort(lx);
}

// ===================== bf16x3 mma.sync GEMM v4 (validated, unchanged) ======
#define APITCH   40
#define A_U16    (64 * APITCH)
#define W_U16G   (128 * APITCH)
#define STAGE_U16 (2 * A_U16 + 2 * W_U16G)
#define OFF_AH   0
#define OFF_AL   A_U16
#define OFF_WH   (2 * A_U16)
#define OFF_WL   (2 * A_U16 + W_U16G)
#define GM_SMEM  (3 * STAGE_U16 * 2)

__global__ __launch_bounds__(256, 2) void gemm_v4(
    const __nv_bfloat16* __restrict__ Ahp,
    const __nv_bfloat16* __restrict__ Alp,
    const __nv_bfloat16* __restrict__ Whp,
    const __nv_bfloat16* __restrict__ Wlp,
    const float* __restrict__ b1, const float* __restrict__ b2,
    float* __restrict__ C, int M, int N, int K, int shiftT)
{
    extern __shared__ __align__(16) uint16_t sm16[];

    const int tid  = threadIdx.x;
    const int lane = tid & 31;
    const int wid  = tid >> 5;
    const int wm   = (wid & 1) * 32;
    const int wn   = (wid >> 1) * 32;
    const int row0 = blockIdx.y * 64;
    const int col0 = blockIdx.x * 128;

    float c[2][4][4];
#pragma unroll
    for (int i = 0; i < 2; i++)
#pragma unroll
        for (int j = 0; j < 4; j++)
#pragma unroll
            for (int q = 0; q < 4; q++) c[i][j][q] = 0.0f;

    const int nch = K / 32;

    const int ar = tid >> 2;
    const int ac = (tid & 3) * 8;
    int grow = row0 + ar;
    int srow = grow, ssz = 16;
    if (shiftT) {
        if ((grow % shiftT) == 0) ssz = 0;
        else srow = grow - 1;
    }

    auto issue = [&](int i) {
        uint16_t* st = sm16 + (i % 3) * STAGE_U16;
        const uint32_t sb = smem_u32(st);
        const int k0 = i * 32;
        uint32_t da = sb + (uint32_t)((ar * APITCH + ac) * 2);
        CP_A16(da + OFF_AH * 2, (const void*)&Ahp[(size_t)srow * K + k0 + ac], ssz);
        CP_A16(da + OFF_AL * 2, (const void*)&Alp[(size_t)srow * K + k0 + ac], ssz);
#pragma unroll
        for (int q = 0; q < 4; q++) {
            int e  = q * 256 + tid;
            int pl = e >> 9;
            int rr = (e >> 2) & 127;
            int cc = (e & 3) * 8;
            const __nv_bfloat16* Wp = pl ? Wlp : Whp;
            uint32_t dw = sb + (uint32_t)((pl ? OFF_WL : OFF_WH) * 2)
                        + (uint32_t)((rr * APITCH + cc) * 2);
            CP_A16(dw, (const void*)&Wp[(size_t)(col0 + rr) * K + k0 + cc], 16);
        }
    };

    issue(0);
    CP_COMMIT();
    if (nch > 1) issue(1);
    CP_COMMIT();

    for (int i = 0; i < nch; i++) {
        CP_WAIT1();
        __syncthreads();
        const uint32_t base = smem_u32(sm16 + (i % 3) * STAGE_U16);
#pragma unroll
        for (int kh = 0; kh < 2; kh++) {
            uint32_t ah[2][4], al[2][4];
            const int arow = wm + (lane & 15);
            const int akk  = kh * 16 + (lane >> 4) * 8;
#pragma unroll
            for (int mt = 0; mt < 2; mt++) {
                uint32_t boff = (uint32_t)(((arow + mt * 16) * APITCH + akk) * 2);
                LDSM4(ah[mt], base + OFF_AH * 2 + boff);
                LDSM4(al[mt], base + OFF_AL * 2 + boff);
            }
            uint32_t bh[2][4], bl[2][4];
            const int brow = wn + (lane & 7) + ((lane >> 4) << 3);
            const int bkk  = kh * 16 + ((lane >> 3) & 1) * 8;
#pragma unroll
            for (int np = 0; np < 2; np++) {
                uint32_t boff = (uint32_t)(((brow + np * 16) * APITCH + bkk) * 2);
                LDSM4(bh[np], base + OFF_WH * 2 + boff);
                LDSM4(bl[np], base + OFF_WL * 2 + boff);
            }
#pragma unroll
            for (int mt = 0; mt < 2; mt++)
#pragma unroll
                for (int np = 0; np < 2; np++)
#pragma unroll
                    for (int h = 0; h < 2; h++) {
                        int nt = np * 2 + h;
                        MMA_BF16(c[mt][nt], ah[mt], bh[np][h * 2], bh[np][h * 2 + 1]);
                        MMA_BF16(c[mt][nt], ah[mt], bl[np][h * 2], bl[np][h * 2 + 1]);
                        MMA_BF16(c[mt][nt], al[mt], bh[np][h * 2], bh[np][h * 2 + 1]);
                    }
        }
        if (i + 2 < nch) issue(i + 2);
        CP_COMMIT();
    }

#pragma unroll
    for (int mt = 0; mt < 2; mt++) {
#pragma unroll
        for (int nt = 0; nt < 4; nt++) {
            int m = row0 + wm + mt * 16 + (lane >> 2);
            int n = col0 + wn + nt * 8 + (lane & 3) * 2;
            float bx = b1[n]     + (b2 ? b2[n]     : 0.f);
            float by = b1[n + 1] + (b2 ? b2[n + 1] : 0.f);
            float2 v0 = make_float2(c[mt][nt][0] + bx, c[mt][nt][1] + by);
            float2 v1 = make_float2(c[mt][nt][2] + bx, c[mt][nt][3] + by);
            *(float2*)&C[(size_t)m * N + n]       = v0;
            *(float2*)&C[(size_t)(m + 8) * N + n] = v1;
        }
    }
}

// ===================== tensor-core persistent LSTM scan v10 ================
// Identical to R12's v8 (aliased gate buffer, GPITCH 18, cp.async staging)
// EXCEPT the barrier: slot barrier — each CTA release-stores its own slot,
// warp 0 polls all 32 slots (lane-parallel + __all_sync), CTA joins via
// __syncthreads. No serialized RMW chain, 16x less poll traffic.
#define WPITCH 520
#define W_U16S (64 * WPITCH)
#define H_U16S (32 * WPITCH)
#define GPITCH 18
#define GQ     (4 * 32 * GPITCH)
#define SCAN_SMEM ((2 * W_U16S + 2 * H_U16S) * 2)

__global__ __launch_bounds__(512, 1) void lstm_scan(
    const float* __restrict__ pre,            // [B,T,4H]
    const float* __restrict__ Whh,            // [4H,H] fp32 (split once here)
    const __nv_bfloat16* __restrict__ h0h,    // initial hidden planes or null
    const __nv_bfloat16* __restrict__ h0l,
    long long h0s,
    const float* __restrict__ cinit,          // [B,H] initial cell or null
    __nv_bfloat16* __restrict__ ph,           // output hidden planes [B,T,H]
    __nv_bfloat16* __restrict__ pl,
    unsigned* __restrict__ bar)               // layer base: group g slots at g*32..+31
{
    extern __shared__ __align__(16) uint16_t sm16[];
    uint16_t* wsh = sm16;
    uint16_t* wsl = wsh + W_U16S;
    uint16_t* hsh = wsl + W_U16S;
    uint16_t* hsl = hsh + H_U16S;
    float*    gsm = (float*)hsh;              // ALIASED over h region (R12 layout)

    const int tid  = threadIdx.x;
    const int lane = tid & 31;
    const int wid  = tid >> 5;
    const int gate = wid & 3;
    const int kbase = (wid >> 2) * 128;
    const int grp  = blockIdx.x;
    const int bi0  = grp * 32;
    const int hc0  = blockIdx.y * 16;
    unsigned* slots  = bar + grp * 32;        // 32 slots = one 128B line
    unsigned* myslot = slots + blockIdx.y;

    // ---- load + split Whh slice once ----
    for (int idx = tid * 4; idx < 64 * 512; idx += 512 * 4) {
        int r  = idx >> 9;
        int k  = idx & 511;
        int gt = r >> 4;
        int rr = r & 15;
        float4 v = *(const float4*)&Whh[((size_t)gt * HH + hc0 + rr) * HH + k];
        uint32_t h0w, l0w, h1w, l1w;
        split2(v.x, v.y, h0w, l0w);
        split2(v.z, v.w, h1w, l1w);
        *(uint2*)&wsh[r * WPITCH + k] = make_uint2(h0w, h1w);
        *(uint2*)&wsl[r * WPITCH + k] = make_uint2(l0w, l1w);
    }

    const int j   = tid & 15;
    const int bl_ = tid >> 4;
    const int b_g = bi0 + bl_;
    const int col = hc0 + j;
    float c_r = cinit ? cinit[b_g * HH + col] : 0.0f;

    const uint32_t hshb = smem_u32(hsh);
    const uint32_t hslb = smem_u32(hsl);
    const uint32_t wshb = smem_u32(wsh);
    const uint32_t wslb = smem_u32(wsl);

    const int arow = lane & 15;
    const int aoff = (lane >> 4) * 8;
    const int brow = gate * 16 + (lane & 7) + ((lane >> 4) << 3);
    const int boff = ((lane >> 3) & 1) * 8;

    for (int t = 0; t < TT; t++) {
        // ---- prefetch pre(t) (h-independent; overlaps poll) ----
        float pr[4];
        {
            size_t prow = ((size_t)b_g * TT + t) * (size_t)G4;
#pragma unroll
            for (int g = 0; g < 4; g++)
                pr[g] = pre[prow + g * HH + col];
        }

        // ---- slot barrier wait: warp 0 polls all 32 slots, CTA joins ----
        if (t > 0) {
            if (wid == 0) {
                unsigned v;
                do {
                    asm volatile("ld.acquire.gpu.global.u32 %0, [%1];"
                                 : "=r"(v) : "l"(slots + lane) : "memory");
                } while (!__all_sync(0xffffffffu, v >= (unsigned)t));
            }
            __syncthreads();
        }

        // ---- stage h(t-1) via cp.async (global -> smem) ----
#pragma unroll
        for (int p = 0; p < 4; p++) {
            int e  = p * 512 + tid;
            int r  = e >> 6;
            int c8 = (e & 63) * 8;
            uint32_t d = (uint32_t)((r * WPITCH + c8) * 2);
            if (t == 0) {
                if (h0h) {
                    CP_A16(hshb + d, (const void*)&h0h[(size_t)(bi0 + r) * h0s + c8], 16);
                    CP_A16(hslb + d, (const void*)&h0l[(size_t)(bi0 + r) * h0s + c8], 16);
                } else {
                    CP_A16(hshb + d, (const void*)ph, 0);
                    CP_A16(hslb + d, (const void*)pl, 0);
                }
            } else {
                size_t off = ((size_t)(bi0 + r) * TT + (t - 1)) * HH + c8;
                CP_A16(hshb + d, (const void*)&ph[off], 16);
                CP_A16(hslb + d, (const void*)&pl[off], 16);
            }
        }
        CP_COMMIT();
        CP_WAIT0();
        __syncthreads();

        // ---- mma: this warp's gate over its K quarter ----
        float c[2][2][4];
#pragma unroll
        for (int mt = 0; mt < 2; mt++)
#pragma unroll
            for (int nt = 0; nt < 2; nt++)
#pragma unroll
                for (int q = 0; q < 4; q++) c[mt][nt][q] = 0.0f;

#pragma unroll
        for (int q = 0; q < 8; q++) {
            int kc = kbase + q * 16;
            uint32_t ah[2][4], al[2][4], bh4[4], bl4[4];
#pragma unroll
            for (int mt = 0; mt < 2; mt++) {
                uint32_t off = (uint32_t)(((mt * 16 + arow) * WPITCH + kc + aoff) * 2);
                LDSM4(ah[mt], hshb + off);
                LDSM4(al[mt], hslb + off);
            }
            {
                uint32_t off = (uint32_t)((brow * WPITCH + kc + boff) * 2);
                LDSM4(bh4, wshb + off);
                LDSM4(bl4, wslb + off);
            }
#pragma unroll
            for (int mt = 0; mt < 2; mt++)
#pragma unroll
                for (int h = 0; h < 2; h++) {
                    MMA_BF16(c[mt][h], ah[mt], bh4[h * 2], bh4[h * 2 + 1]);
                    MMA_BF16(c[mt][h], ah[mt], bl4[h * 2], bl4[h * 2 + 1]);
                    MMA_BF16(c[mt][h], al[mt], bh4[h * 2], bh4[h * 2 + 1]);
                }
        }
        __syncthreads();   // all mma reads of h done before gsm overwrite

        // ---- fragments -> aliased gate buffer (own quarter section) ----
        float* gq = gsm + (wid >> 2) * GQ;
#pragma unroll
        for (int mt = 0; mt < 2; mt++)
#pragma unroll
            for (int nt = 0; nt < 2; nt++) {
                int m = mt * 16 + (lane >> 2);
                int n = nt * 8 + (lane & 3) * 2;
                float* gbase = gq + (gate * 32 + m) * GPITCH + n;
                *(float2*)gbase                = make_float2(c[mt][nt][0], c[mt][nt][1]);
                *(float2*)(gbase + 8 * GPITCH) = make_float2(c[mt][nt][2], c[mt][nt][3]);
            }
        __syncthreads();

        // ---- gates + state update: one (b, col) per thread ----
        {
            float gv[4];
#pragma unroll
            for (int g = 0; g < 4; g++) {
                float s = pr[g];
#pragma unroll
                for (int q = 0; q < 4; q++)
                    s += gsm[q * GQ + (g * 32 + bl_) * GPITCH + j];
                gv[g] = s;
            }
            float i_ = 1.0f / (1.0f + __expf(-gv[0]));
            float f_ = 1.0f / (1.0f + __expf(-gv[1]));
            float e2 = __expf(2.0f * gv[2]);
            float g_ = (e2 - 1.0f) / (e2 + 1.0f);
            float o_ = 1.0f / (1.0f + __expf(-gv[3]));

            float cn = f_ * c_r + i_ * g_;
            c_r = cn;
            float ec = __expf(2.0f * cn);
            float th = (ec - 1.0f) / (ec + 1.0f);
            float hv = o_ * th;

            __nv_bfloat16 hh = __float2bfloat16_rn(hv);
            __nv_bfloat16 hl = __float2bfloat16_rn(hv - __bfloat162float(hh));
            size_t off = ((size_t)b_g * TT + t) * HH + col;
            ph[off] = hh;
            pl[off] = hl;
        }

        // ---- arrive: release-store own slot (h stores ordered by sync) ----
        __syncthreads();
        if (tid == 0)
            asm volatile("st.release.gpu.global.u32 [%0], %1;"
                         :: "l"(myslot), "r"((unsigned)(t + 1)) : "memory");
    }
}

// ---------------- host driver --------------------------------------------
extern "C" void kernel_launch(void* const* d_in, const int* in_sizes, int n_in,
                              void* d_out, int out_size)
{
    const float* x     = (const float*)d_in[0];
    const float* c_dec = (const float*)d_in[1];
    const float* eWih0 = (const float*)d_in[2];
    const float* eWhh0 = (const float*)d_in[3];
    const float* ebih0 = (const float*)d_in[4];
    const float* ebhh0 = (const float*)d_in[5];
    const float* eWih1 = (const float*)d_in[6];
    const float* eWhh1 = (const float*)d_in[7];
    const float* ebih1 = (const float*)d_in[8];
    const float* ebhh1 = (const float*)d_in[9];
    const float* dWih0 = (const float*)d_in[10];
    const float* dWhh0 = (const float*)d_in[11];
    const float* dbih0 = (const float*)d_in[12];
    const float* dbhh0 = (const float*)d_in[13];
    const float* dWih1 = (const float*)d_in[14];
    const float* dWhh1 = (const float*)d_in[15];
    const float* dbih1 = (const float*)d_in[16];
    const float* dbhh1 = (const float*)d_in[17];
    const float* fcW   = (const float*)d_in[18];
    const float* fcB   = (const float*)d_in[19];
    float*       out   = (float*)d_out;

    static float *pre = nullptr;
    static __nv_bfloat16 *bXh, *bXl, *bYh, *bYl, *xh, *xl, *wh, *wl;
    static unsigned *bars = nullptr;
    static bool inited = false;
    if (!inited) {
        cudaGetSymbolAddress((void**)&pre,  g_pre);
        cudaGetSymbolAddress((void**)&bXh,  g_bufXh);
        cudaGetSymbolAddress((void**)&bXl,  g_bufXl);
        cudaGetSymbolAddress((void**)&bYh,  g_bufYh);
        cudaGetSymbolAddress((void**)&bYl,  g_bufYl);
        cudaGetSymbolAddress((void**)&xh,   g_xh);
        cudaGetSymbolAddress((void**)&xl,   g_xl);
        cudaGetSymbolAddress((void**)&wh,   g_wh);
        cudaGetSymbolAddress((void**)&wl,   g_wl);
        cudaGetSymbolAddress((void**)&bars, g_barrier);
        cudaFuncSetAttribute(lstm_scan,
                             cudaFuncAttributeMaxDynamicSharedMemorySize, SCAN_SMEM);
        cudaFuncSetAttribute(gemm_v4,
                             cudaFuncAttributeMaxDynamicSharedMemorySize, GM_SMEM);
        inited = true;
    }

    const int M = BB * TT;
    const dim3 gemmGrid2048(G4 / 128, M / 64);
    const dim3 gemmGrid128(II / 128,  M / 64);
    const dim3 scanGrid(4, 32);
    const long long seqStride = (long long)TT * HH;

    zero_bar<<<2, 256>>>(bars, 512);

    // ---- pre-split x and all feed-forward weights into bf16 planes ----
    split_planes<<<(M * II + 255) / 256, 256>>>(x, xh, xl, M * II);
    split_planes<<<(2048 * 128 + 255) / 256, 256>>>(eWih0, wh + WO0, wl + WO0, 2048 * 128);
    split_planes<<<(2048 * 512 + 255) / 256, 256>>>(eWih1, wh + WO1, wl + WO1, 2048 * 512);
    split_planes<<<(2048 * 128 + 255) / 256, 256>>>(dWih0, wh + WO2, wl + WO2, 2048 * 128);
    split_planes<<<(2048 * 512 + 255) / 256, 256>>>(dWih1, wh + WO3, wl + WO3, 2048 * 512);
    split_planes<<<(128 * 512 + 255) / 256, 256>>>(fcW,   wh + WO4, wl + WO4, 128 * 512);

    // ---- encoder layer 0 (A = x planes) ----
    gemm_v4<<<gemmGrid2048, 256, GM_SMEM>>>(
        xh, xl, wh + WO0, wl + WO0, ebih0, ebhh0, pre, M, G4, II, 0);
    lstm_scan<<<scanGrid, 512, SCAN_SMEM>>>(pre, eWhh0, nullptr, nullptr, 0, nullptr,
                                            bXh, bXl, bars + 0 * 128);

    // ---- encoder layer 1 (A = bufX planes) ----
    gemm_v4<<<gemmGrid2048, 256, GM_SMEM>>>(
        bXh, bXl, wh + WO1, wl + WO1, ebih1, ebhh1, pre, M, G4, HH, 0);
    lstm_scan<<<scanGrid, 512, SCAN_SMEM>>>(pre, eWhh1, nullptr, nullptr, 0, nullptr,
                                            bYh, bYl, bars + 1 * 128);

    // ---- decoder layer 0 (A = x planes shifted; h0 = enc0 final row) ----
    gemm_v4<<<gemmGrid2048, 256, GM_SMEM>>>(
        xh, xl, wh + WO2, wl + WO2, dbih0, dbhh0, pre, M, G4, II, TT);
    lstm_scan<<<scanGrid, 512, SCAN_SMEM>>>(pre, dWhh0,
                                            bXh + (size_t)(TT - 1) * HH,
                                            bXl + (size_t)(TT - 1) * HH,
                                            seqStride, c_dec,
                                            bXh, bXl, bars + 2 * 128);

    // ---- decoder layer 1 (A = bufX planes; h0 = enc1 final row) ----
    gemm_v4<<<gemmGrid2048, 256, GM_SMEM>>>(
        bXh, bXl, wh + WO3, wl + WO3, dbih1, dbhh1, pre, M, G4, HH, 0);
    lstm_scan<<<scanGrid, 512, SCAN_SMEM>>>(pre, dWhh1,
                                            bYh + (size_t)(TT - 1) * HH,
                                            bYl + (size_t)(TT - 1) * HH,
                                            seqStride, c_dec + BB * HH,
                                            bYh, bYl, bars + 3 * 128);

    // ---- FC head (A = bufY planes) ----
    gemm_v4<<<gemmGrid128, 256, GM_SMEM>>>(
        bYh, bYl, wh + WO4, wl + WO4, fcB, nullptr, out, M, II, HH, 0);
}

// round 15
// speedup vs baseline: 1.1253x; 1.1253x over previous
#include <cuda_runtime.h>
#include <cuda_bf16.h>
#include <math.h>
#include <stdint.h>

// Problem constants
#define BB   128      // batch
#define TT   512      // time steps
#define HH   512      // hidden
#define II   128      // input dim
#define G4   2048     // 4*H

// ---------------- scratch (static device memory; no allocations) ----------
__device__ float g_pre [(size_t)BB * TT * G4];
__device__ __align__(16) __nv_bfloat16 g_bufXh[(size_t)BB * TT * HH];
__device__ __align__(16) __nv_bfloat16 g_bufXl[(size_t)BB * TT * HH];
__device__ __align__(16) __nv_bfloat16 g_bufYh[(size_t)BB * TT * HH];
__device__ __align__(16) __nv_bfloat16 g_bufYl[(size_t)BB * TT * HH];
__device__ __align__(16) __nv_bfloat16 g_xh[(size_t)BB * TT * II];
__device__ __align__(16) __nv_bfloat16 g_xl[(size_t)BB * TT * II];
// weight planes: [enc0 2048x128][enc1 2048x512][dec0 2048x128][dec1 2048x512][fc 128x512]
#define WO0 0
#define WO1 (WO0 + 2048 * 128)
#define WO2 (WO1 + 2048 * 512)
#define WO3 (WO2 + 2048 * 128)
#define WO4 (WO3 + 2048 * 512)
#define WTOT (WO4 + 128 * 512)
__device__ __align__(16) __nv_bfloat16 g_wh[WTOT];
__device__ __align__(16) __nv_bfloat16 g_wl[WTOT];
__device__ unsigned g_barrier[1024];  // 4 layers x 4 groups: counter g*64, flag g*64+32

// ---------------- tiny init kernels ----------------------------------------
__global__ void zero_bar(unsigned* p, int n) {
    int i = blockIdx.x * blockDim.x + threadIdx.x;
    if (i < n) p[i] = 0u;
}
__global__ void split_planes(const float* __restrict__ in,
                             __nv_bfloat16* __restrict__ oh,
                             __nv_bfloat16* __restrict__ ol, int n) {
    int i = blockIdx.x * blockDim.x + threadIdx.x;
    if (i < n) {
        float v = in[i];
        __nv_bfloat16 h = __float2bfloat16_rn(v);
        oh[i] = h;
        ol[i] = __float2bfloat16_rn(v - __bfloat162float(h));
    }
}

// ======================= helpers (compute_103-safe) ========================
__device__ __forceinline__ uint32_t smem_u32(const void* p) {
    return (uint32_t)__cvta_generic_to_shared(p);
}

#define LDSM4(d, addr)                                                        \
    asm volatile("ldmatrix.sync.aligned.m8n8.x4.shared.b16 "                  \
                 "{%0,%1,%2,%3}, [%4];"                                       \
                 : "=r"((d)[0]), "=r"((d)[1]), "=r"((d)[2]), "=r"((d)[3])     \
                 : "r"(addr))

#define MMA_BF16(cc, a, bb0, bb1)                                             \
    asm volatile("mma.sync.aligned.m16n8k16.row.col.f32.bf16.bf16.f32 "       \
                 "{%0,%1,%2,%3}, {%4,%5,%6,%7}, {%8,%9}, {%0,%1,%2,%3};"      \
                 : "+f"((cc)[0]), "+f"((cc)[1]), "+f"((cc)[2]), "+f"((cc)[3]) \
                 : "r"((a)[0]), "r"((a)[1]), "r"((a)[2]), "r"((a)[3]),        \
                   "r"(bb0), "r"(bb1))

#define CP_A16(dst, src, sz)                                                  \
    asm volatile("cp.async.cg.shared.global [%0], [%1], 16, %2;"              \
                 :: "r"(dst), "l"(src), "r"(sz) : "memory")
#define CP_COMMIT() asm volatile("cp.async.commit_group;" ::: "memory")
#define CP_WAIT1()  asm volatile("cp.async.wait_group 1;" ::: "memory")
#define CP_WAIT0()  asm volatile("cp.async.wait_group 0;" ::: "memory")

__device__ __forceinline__ void split2(float x, float y,
                                       uint32_t& hi, uint32_t& lo) {
    __nv_bfloat16 hx = __float2bfloat16_rn(x);
    __nv_bfloat16 hy = __float2bfloat16_rn(y);
    __nv_bfloat16 lx = __float2bfloat16_rn(x - __bfloat162float(hx));
    __nv_bfloat16 ly = __float2bfloat16_rn(y - __bfloat162float(hy));
    hi = ((uint32_t)__bfloat16_as_ushort(hy) << 16) | __bfloat16_as_ushort(hx);
    lo = ((uint32_t)__bfloat16_as_ushort(ly) << 16) | __bfloat16_as_ushort(lx);
}

// ===================== bf16x3 mma.sync GEMM v4 (validated, unchanged) ======
#define APITCH   40
#define A_U16    (64 * APITCH)
#define W_U16G   (128 * APITCH)
#define STAGE_U16 (2 * A_U16 + 2 * W_U16G)
#define OFF_AH   0
#define OFF_AL   A_U16
#define OFF_WH   (2 * A_U16)
#define OFF_WL   (2 * A_U16 + W_U16G)
#define GM_SMEM  (3 * STAGE_U16 * 2)

__global__ __launch_bounds__(256, 2) void gemm_v4(
    const __nv_bfloat16* __restrict__ Ahp,
    const __nv_bfloat16* __restrict__ Alp,
    const __nv_bfloat16* __restrict__ Whp,
    const __nv_bfloat16* __restrict__ Wlp,
    const float* __restrict__ b1, const float* __restrict__ b2,
    float* __restrict__ C, int M, int N, int K, int shiftT)
{
    extern __shared__ __align__(16) uint16_t sm16[];

    const int tid  = threadIdx.x;
    const int lane = tid & 31;
    const int wid  = tid >> 5;
    const int wm   = (wid & 1) * 32;
    const int wn   = (wid >> 1) * 32;
    const int row0 = blockIdx.y * 64;
    const int col0 = blockIdx.x * 128;

    float c[2][4][4];
#pragma unroll
    for (int i = 0; i < 2; i++)
#pragma unroll
        for (int j = 0; j < 4; j++)
#pragma unroll
            for (int q = 0; q < 4; q++) c[i][j][q] = 0.0f;

    const int nch = K / 32;

    const int ar = tid >> 2;
    const int ac = (tid & 3) * 8;
    int grow = row0 + ar;
    int srow = grow, ssz = 16;
    if (shiftT) {
        if ((grow % shiftT) == 0) ssz = 0;
        else srow = grow - 1;
    }

    auto issue = [&](int i) {
        uint16_t* st = sm16 + (i % 3) * STAGE_U16;
        const uint32_t sb = smem_u32(st);
        const int k0 = i * 32;
        uint32_t da = sb + (uint32_t)((ar * APITCH + ac) * 2);
        CP_A16(da + OFF_AH * 2, (const void*)&Ahp[(size_t)srow * K + k0 + ac], ssz);
        CP_A16(da + OFF_AL * 2, (const void*)&Alp[(size_t)srow * K + k0 + ac], ssz);
#pragma unroll
        for (int q = 0; q < 4; q++) {
            int e  = q * 256 + tid;
            int pl = e >> 9;
            int rr = (e >> 2) & 127;
            int cc = (e & 3) * 8;
            const __nv_bfloat16* Wp = pl ? Wlp : Whp;
            uint32_t dw = sb + (uint32_t)((pl ? OFF_WL : OFF_WH) * 2)
                        + (uint32_t)((rr * APITCH + cc) * 2);
            CP_A16(dw, (const void*)&Wp[(size_t)(col0 + rr) * K + k0 + cc], 16);
        }
    };

    issue(0);
    CP_COMMIT();
    if (nch > 1) issue(1);
    CP_COMMIT();

    for (int i = 0; i < nch; i++) {
        CP_WAIT1();
        __syncthreads();
        const uint32_t base = smem_u32(sm16 + (i % 3) * STAGE_U16);
#pragma unroll
        for (int kh = 0; kh < 2; kh++) {
            uint32_t ah[2][4], al[2][4];
            const int arow = wm + (lane & 15);
            const int akk  = kh * 16 + (lane >> 4) * 8;
#pragma unroll
            for (int mt = 0; mt < 2; mt++) {
                uint32_t boff = (uint32_t)(((arow + mt * 16) * APITCH + akk) * 2);
                LDSM4(ah[mt], base + OFF_AH * 2 + boff);
                LDSM4(al[mt], base + OFF_AL * 2 + boff);
            }
            uint32_t bh[2][4], bl[2][4];
            const int brow = wn + (lane & 7) + ((lane >> 4) << 3);
            const int bkk  = kh * 16 + ((lane >> 3) & 1) * 8;
#pragma unroll
            for (int np = 0; np < 2; np++) {
                uint32_t boff = (uint32_t)(((brow + np * 16) * APITCH + bkk) * 2);
                LDSM4(bh[np], base + OFF_WH * 2 + boff);
                LDSM4(bl[np], base + OFF_WL * 2 + boff);
            }
#pragma unroll
            for (int mt = 0; mt < 2; mt++)
#pragma unroll
                for (int np = 0; np < 2; np++)
#pragma unroll
                    for (int h = 0; h < 2; h++) {
                        int nt = np * 2 + h;
                        MMA_BF16(c[mt][nt], ah[mt], bh[np][h * 2], bh[np][h * 2 + 1]);
                        MMA_BF16(c[mt][nt], ah[mt], bl[np][h * 2], bl[np][h * 2 + 1]);
                        MMA_BF16(c[mt][nt], al[mt], bh[np][h * 2], bh[np][h * 2 + 1]);
                    }
        }
        if (i + 2 < nch) issue(i + 2);
        CP_COMMIT();
    }

#pragma unroll
    for (int mt = 0; mt < 2; mt++) {
#pragma unroll
        for (int nt = 0; nt < 4; nt++) {
            int m = row0 + wm + mt * 16 + (lane >> 2);
            int n = col0 + wn + nt * 8 + (lane & 3) * 2;
            float bx = b1[n]     + (b2 ? b2[n]     : 0.f);
            float by = b1[n + 1] + (b2 ? b2[n + 1] : 0.f);
            float2 v0 = make_float2(c[mt][nt][0] + bx, c[mt][nt][1] + by);
            float2 v1 = make_float2(c[mt][nt][2] + bx, c[mt][nt][3] + by);
            *(float2*)&C[(size_t)m * N + n]       = v0;
            *(float2*)&C[(size_t)(m + 8) * N + n] = v1;
        }
    }
}

// ===================== tensor-core persistent LSTM scan v11 ================
// EXACT R12 kernel (counter+flag barrier, aliased gate buffer, GPITCH 18,
// cp.async staging) with ONE change: the flag wait is polled by warp 0 only
// (one coalesced L2 request per CTA per iteration, 16x less flag-line read
// interference with the release store); other warps join via __syncthreads.
#define WPITCH 520
#define W_U16S (64 * WPITCH)
#define H_U16S (32 * WPITCH)
#define GPITCH 18
#define GQ     (4 * 32 * GPITCH)
#define SCAN_SMEM ((2 * W_U16S + 2 * H_U16S) * 2)

__global__ __launch_bounds__(512, 1) void lstm_scan(
    const float* __restrict__ pre,            // [B,T,4H]
    const float* __restrict__ Whh,            // [4H,H] fp32 (split once here)
    const __nv_bfloat16* __restrict__ h0h,    // initial hidden planes or null
    const __nv_bfloat16* __restrict__ h0l,
    long long h0s,
    const float* __restrict__ cinit,          // [B,H] initial cell or null
    __nv_bfloat16* __restrict__ ph,           // output hidden planes [B,T,H]
    __nv_bfloat16* __restrict__ pl,
    unsigned* __restrict__ bar)               // group g: counter g*64, flag g*64+32
{
    extern __shared__ __align__(16) uint16_t sm16[];
    uint16_t* wsh = sm16;
    uint16_t* wsl = wsh + W_U16S;
    uint16_t* hsh = wsl + W_U16S;
    uint16_t* hsl = hsh + H_U16S;
    float*    gsm = (float*)hsh;              // ALIASED over h region

    const int tid  = threadIdx.x;
    const int lane = tid & 31;
    const int wid  = tid >> 5;
    const int gate = wid & 3;
    const int kbase = (wid >> 2) * 128;
    const int grp  = blockIdx.x;
    const int bi0  = grp * 32;
    const int hc0  = blockIdx.y * 16;
    unsigned* ctr  = bar + grp * 64;
    unsigned* flag = ctr + 32;

    // ---- load + split Whh slice once ----
    for (int idx = tid * 4; idx < 64 * 512; idx += 512 * 4) {
        int r  = idx >> 9;
        int k  = idx & 511;
        int gt = r >> 4;
        int rr = r & 15;
        float4 v = *(const float4*)&Whh[((size_t)gt * HH + hc0 + rr) * HH + k];
        uint32_t h0w, l0w, h1w, l1w;
        split2(v.x, v.y, h0w, l0w);
        split2(v.z, v.w, h1w, l1w);
        *(uint2*)&wsh[r * WPITCH + k] = make_uint2(h0w, h1w);
        *(uint2*)&wsl[r * WPITCH + k] = make_uint2(l0w, l1w);
    }

    const int j   = tid & 15;
    const int bl_ = tid >> 4;
    const int b_g = bi0 + bl_;
    const int col = hc0 + j;
    float c_r = cinit ? cinit[b_g * HH + col] : 0.0f;

    const uint32_t hshb = smem_u32(hsh);
    const uint32_t hslb = smem_u32(hsl);
    const uint32_t wshb = smem_u32(wsh);
    const uint32_t wslb = smem_u32(wsl);

    const int arow = lane & 15;
    const int aoff = (lane >> 4) * 8;
    const int brow = gate * 16 + (lane & 7) + ((lane >> 4) << 3);
    const int boff = ((lane >> 3) & 1) * 8;

    for (int t = 0; t < TT; t++) {
        // ---- prefetch pre(t) (h-independent; overlaps poll) ----
        float pr[4];
        {
            size_t prow = ((size_t)b_g * TT + t) * (size_t)G4;
#pragma unroll
            for (int g = 0; g < 4; g++)
                pr[g] = pre[prow + g * HH + col];
        }

        // ---- wait: warp 0 polls the flag (1 coalesced req/iter), CTA joins ----
        if (t > 0) {
            if (wid == 0) {
                unsigned v;
                do {
                    asm volatile("ld.acquire.gpu.global.u32 %0, [%1];"
                                 : "=r"(v) : "l"(flag) : "memory");
                } while (v < (unsigned)t);
            }
            __syncthreads();
        }

        // ---- stage h(t-1) via cp.async (global -> smem) ----
#pragma unroll
        for (int p = 0; p < 4; p++) {
            int e  = p * 512 + tid;
            int r  = e >> 6;
            int c8 = (e & 63) * 8;
            uint32_t d = (uint32_t)((r * WPITCH + c8) * 2);
            if (t == 0) {
                if (h0h) {
                    CP_A16(hshb + d, (const void*)&h0h[(size_t)(bi0 + r) * h0s + c8], 16);
                    CP_A16(hslb + d, (const void*)&h0l[(size_t)(bi0 + r) * h0s + c8], 16);
                } else {
                    CP_A16(hshb + d, (const void*)ph, 0);
                    CP_A16(hslb + d, (const void*)pl, 0);
                }
            } else {
                size_t off = ((size_t)(bi0 + r) * TT + (t - 1)) * HH + c8;
                CP_A16(hshb + d, (const void*)&ph[off], 16);
                CP_A16(hslb + d, (const void*)&pl[off], 16);
            }
        }
        CP_COMMIT();
        CP_WAIT0();
        __syncthreads();

        // ---- mma: this warp's gate over its K quarter ----
        float c[2][2][4];
#pragma unroll
        for (int mt = 0; mt < 2; mt++)
#pragma unroll
            for (int nt = 0; nt < 2; nt++)
#pragma unroll
                for (int q = 0; q < 4; q++) c[mt][nt][q] = 0.0f;

#pragma unroll
        for (int q = 0; q < 8; q++) {
            int kc = kbase + q * 16;
            uint32_t ah[2][4], al[2][4], bh4[4], bl4[4];
#pragma unroll
            for (int mt = 0; mt < 2; mt++) {
                uint32_t off = (uint32_t)(((mt * 16 + arow) * WPITCH + kc + aoff) * 2);
                LDSM4(ah[mt], hshb + off);
                LDSM4(al[mt], hslb + off);
            }
            {
                uint32_t off = (uint32_t)((brow * WPITCH + kc + boff) * 2);
                LDSM4(bh4, wshb + off);
                LDSM4(bl4, wslb + off);
            }
#pragma unroll
            for (int mt = 0; mt < 2; mt++)
#pragma unroll
                for (int h = 0; h < 2; h++) {
                    MMA_BF16(c[mt][h], ah[mt], bh4[h * 2], bh4[h * 2 + 1]);
                    MMA_BF16(c[mt][h], ah[mt], bl4[h * 2], bl4[h * 2 + 1]);
                    MMA_BF16(c[mt][h], al[mt], bh4[h * 2], bh4[h * 2 + 1]);
                }
        }
        __syncthreads();   // all mma reads of h done before gsm overwrite

        // ---- fragments -> aliased gate buffer (own quarter section) ----
        float* gq = gsm + (wid >> 2) * GQ;
#pragma unroll
        for (int mt = 0; mt < 2; mt++)
#pragma unroll
            for (int nt = 0; nt < 2; nt++) {
                int m = mt * 16 + (lane >> 2);
                int n = nt * 8 + (lane & 3) * 2;
                float* gbase = gq + (gate * 32 + m) * GPITCH + n;
                *(float2*)gbase                = make_float2(c[mt][nt][0], c[mt][nt][1]);
                *(float2*)(gbase + 8 * GPITCH) = make_float2(c[mt][nt][2], c[mt][nt][3]);
            }
        __syncthreads();

        // ---- gates + state update: one (b, col) per thread ----
        {
            float gv[4];
#pragma unroll
            for (int g = 0; g < 4; g++) {
                float s = pr[g];
#pragma unroll
                for (int q = 0; q < 4; q++)
                    s += gsm[q * GQ + (g * 32 + bl_) * GPITCH + j];
                gv[g] = s;
            }
            float i_ = 1.0f / (1.0f + __expf(-gv[0]));
            float f_ = 1.0f / (1.0f + __expf(-gv[1]));
            float e2 = __expf(2.0f * gv[2]);
            float g_ = (e2 - 1.0f) / (e2 + 1.0f);
            float o_ = 1.0f / (1.0f + __expf(-gv[3]));

            float cn = f_ * c_r + i_ * g_;
            c_r = cn;
            float ec = __expf(2.0f * cn);
            float th = (ec - 1.0f) / (ec + 1.0f);
            float hv = o_ * th;

            __nv_bfloat16 hh = __float2bfloat16_rn(hv);
            __nv_bfloat16 hl = __float2bfloat16_rn(hv - __bfloat162float(hh));
            size_t off = ((size_t)b_g * TT + t) * HH + col;
            ph[off] = hh;
            pl[off] = hl;
        }

        // ---- arrive: counter RMW; last arriver release-stores the flag ----
        __syncthreads();
        if (tid == 0) {
            unsigned old;
            asm volatile("atom.acq_rel.gpu.global.add.u32 %0, [%1], %2;"
                         : "=r"(old) : "l"(ctr), "r"(1u) : "memory");
            if (old == (unsigned)(t * 32 + 31)) {
                asm volatile("st.release.gpu.global.u32 [%0], %1;"
                             :: "l"(flag), "r"((unsigned)(t + 1)) : "memory");
            }
        }
    }
}

// ---------------- host driver --------------------------------------------
extern "C" void kernel_launch(void* const* d_in, const int* in_sizes, int n_in,
                              void* d_out, int out_size)
{
    const float* x     = (const float*)d_in[0];
    const float* c_dec = (const float*)d_in[1];
    const float* eWih0 = (const float*)d_in[2];
    const float* eWhh0 = (const float*)d_in[3];
    const float* ebih0 = (const float*)d_in[4];
    const float* ebhh0 = (const float*)d_in[5];
    const float* eWih1 = (const float*)d_in[6];
    const float* eWhh1 = (const float*)d_in[7];
    const float* ebih1 = (const float*)d_in[8];
    const float* ebhh1 = (const float*)d_in[9];
    const float* dWih0 = (const float*)d_in[10];
    const float* dWhh0 = (const float*)d_in[11];
    const float* dbih0 = (const float*)d_in[12];
    const float* dbhh0 = (const float*)d_in[13];
    const float* dWih1 = (const float*)d_in[14];
    const float* dWhh1 = (const float*)d_in[15];
    const float* dbih1 = (const float*)d_in[16];
    const float* dbhh1 = (const float*)d_in[17];
    const float* fcW   = (const float*)d_in[18];
    const float* fcB   = (const float*)d_in[19];
    float*       out   = (float*)d_out;

    static float *pre = nullptr;
    static __nv_bfloat16 *bXh, *bXl, *bYh, *bYl, *xh, *xl, *wh, *wl;
    static unsigned *bars = nullptr;
    static bool inited = false;
    if (!inited) {
        cudaGetSymbolAddress((void**)&pre,  g_pre);
        cudaGetSymbolAddress((void**)&bXh,  g_bufXh);
        cudaGetSymbolAddress((void**)&bXl,  g_bufXl);
        cudaGetSymbolAddress((void**)&bYh,  g_bufYh);
        cudaGetSymbolAddress((void**)&bYl,  g_bufYl);
        cudaGetSymbolAddress((void**)&xh,   g_xh);
        cudaGetSymbolAddress((void**)&xl,   g_xl);
        cudaGetSymbolAddress((void**)&wh,   g_wh);
        cudaGetSymbolAddress((void**)&wl,   g_wl);
        cudaGetSymbolAddress((void**)&bars, g_barrier);
        cudaFuncSetAttribute(lstm_scan,
                             cudaFuncAttributeMaxDynamicSharedMemorySize, SCAN_SMEM);
        cudaFuncSetAttribute(gemm_v4,
                             cudaFuncAttributeMaxDynamicSharedMemorySize, GM_SMEM);
        inited = true;
    }

    const int M = BB * TT;
    const dim3 gemmGrid2048(G4 / 128, M / 64);
    const dim3 gemmGrid128(II / 128,  M / 64);
    const dim3 scanGrid(4, 32);
    const long long seqStride = (long long)TT * HH;

    zero_bar<<<4, 256>>>(bars, 1024);

    // ---- pre-split x and all feed-forward weights into bf16 planes ----
    split_planes<<<(M * II + 255) / 256, 256>>>(x, xh, xl, M * II);
    split_planes<<<(2048 * 128 + 255) / 256, 256>>>(eWih0, wh + WO0, wl + WO0, 2048 * 128);
    split_planes<<<(2048 * 512 + 255) / 256, 256>>>(eWih1, wh + WO1, wl + WO1, 2048 * 512);
    split_planes<<<(2048 * 128 + 255) / 256, 256>>>(dWih0, wh + WO2, wl + WO2, 2048 * 128);
    split_planes<<<(2048 * 512 + 255) / 256, 256>>>(dWih1, wh + WO3, wl + WO3, 2048 * 512);
    split_planes<<<(128 * 512 + 255) / 256, 256>>>(fcW,   wh + WO4, wl + WO4, 128 * 512);

    // ---- encoder layer 0 (A = x planes) ----
    gemm_v4<<<gemmGrid2048, 256, GM_SMEM>>>(
        xh, xl, wh + WO0, wl + WO0, ebih0, ebhh0, pre, M, G4, II, 0);
    lstm_scan<<<scanGrid, 512, SCAN_SMEM>>>(pre, eWhh0, nullptr, nullptr, 0, nullptr,
                                            bXh, bXl, bars + 0 * 256);

    // ---- encoder layer 1 (A = bufX planes) ----
    gemm_v4<<<gemmGrid2048, 256, GM_SMEM>>>(
        bXh, bXl, wh + WO1, wl + WO1, ebih1, ebhh1, pre, M, G4, HH, 0);
    lstm_scan<<<scanGrid, 512, SCAN_SMEM>>>(pre, eWhh1, nullptr, nullptr, 0, nullptr,
                                            bYh, bYl, bars + 1 * 256);

    // ---- decoder layer 0 (A = x planes shifted; h0 = enc0 final row) ----
    gemm_v4<<<gemmGrid2048, 256, GM_SMEM>>>(
        xh, xl, wh + WO2, wl + WO2, dbih0, dbhh0, pre, M, G4, II, TT);
    lstm_scan<<<scanGrid, 512, SCAN_SMEM>>>(pre, dWhh0,
                                            bXh + (size_t)(TT - 1) * HH,
                                            bXl + (size_t)(TT - 1) * HH,
                                            seqStride, c_dec,
                                            bXh, bXl, bars + 2 * 256);

    // ---- decoder layer 1 (A = bufX planes; h0 = enc1 final row) ----
    gemm_v4<<<gemmGrid2048, 256, GM_SMEM>>>(
        bXh, bXl, wh + WO3, wl + WO3, dbih1, dbhh1, pre, M, G4, HH, 0);
    lstm_scan<<<scanGrid, 512, SCAN_SMEM>>>(pre, dWhh1,
                                            bYh + (size_t)(TT - 1) * HH,
                                            bYl + (size_t)(TT - 1) * HH,
                                            seqStride, c_dec + BB * HH,
                                            bYh, bYl, bars + 3 * 256);

    // ---- FC head (A = bufY planes) ----
    gemm_v4<<<gemmGrid128, 256, GM_SMEM>>>(
        bYh, bYl, wh + WO4, wl + WO4, fcB, nullptr, out, M, II, HH, 0);
}

// round 16
// speedup vs baseline: 1.1510x; 1.0228x over previous
#include <cuda_runtime.h>
#include <cuda_bf16.h>
#include <math.h>
#include <stdint.h>

// Problem constants
#define BB   128      // batch
#define TT   512      // time steps
#define HH   512      // hidden
#define II   128      // input dim
#define G4   2048     // 4*H

// ---------------- scratch (static device memory; no allocations) ----------
__device__ float g_pre [(size_t)BB * TT * G4];
__device__ float g_pre2[(size_t)BB * TT * G4];   // dec0 projection (overlapped)
__device__ __align__(16) __nv_bfloat16 g_bufXh[(size_t)BB * TT * HH];
__device__ __align__(16) __nv_bfloat16 g_bufXl[(size_t)BB * TT * HH];
__device__ __align__(16) __nv_bfloat16 g_bufYh[(size_t)BB * TT * HH];
__device__ __align__(16) __nv_bfloat16 g_bufYl[(size_t)BB * TT * HH];
__device__ __align__(16) __nv_bfloat16 g_xh[(size_t)BB * TT * II];
__device__ __align__(16) __nv_bfloat16 g_xl[(size_t)BB * TT * II];
// weight planes: [enc0 2048x128][enc1 2048x512][dec0 2048x128][dec1 2048x512][fc 128x512]
#define WO0 0
#define WO1 (WO0 + 2048 * 128)
#define WO2 (WO1 + 2048 * 512)
#define WO3 (WO2 + 2048 * 128)
#define WO4 (WO3 + 2048 * 512)
#define WTOT (WO4 + 128 * 512)
__device__ __align__(16) __nv_bfloat16 g_wh[WTOT];
__device__ __align__(16) __nv_bfloat16 g_wl[WTOT];
__device__ unsigned g_barrier[1024];  // 4 layers x 4 groups: counter g*64, flag g*64+32

// ---------------- tiny init kernels ----------------------------------------
__global__ void zero_bar(unsigned* p, int n) {
    int i = blockIdx.x * blockDim.x + threadIdx.x;
    if (i < n) p[i] = 0u;
}
__global__ void split_planes(const float* __restrict__ in,
                             __nv_bfloat16* __restrict__ oh,
                             __nv_bfloat16* __restrict__ ol, int n) {
    int i = blockIdx.x * blockDim.x + threadIdx.x;
    if (i < n) {
        float v = in[i];
        __nv_bfloat16 h = __float2bfloat16_rn(v);
        oh[i] = h;
        ol[i] = __float2bfloat16_rn(v - __bfloat162float(h));
    }
}

// ======================= helpers (compute_103-safe) ========================
__device__ __forceinline__ uint32_t smem_u32(const void* p) {
    return (uint32_t)__cvta_generic_to_shared(p);
}

#define LDSM4(d, addr)                                                        \
    asm volatile("ldmatrix.sync.aligned.m8n8.x4.shared.b16 "                  \
                 "{%0,%1,%2,%3}, [%4];"                                       \
                 : "=r"((d)[0]), "=r"((d)[1]), "=r"((d)[2]), "=r"((d)[3])     \
                 : "r"(addr))

#define MMA_BF16(cc, a, bb0, bb1)                                             \
    asm volatile("mma.sync.aligned.m16n8k16.row.col.f32.bf16.bf16.f32 "       \
                 "{%0,%1,%2,%3}, {%4,%5,%6,%7}, {%8,%9}, {%0,%1,%2,%3};"      \
                 : "+f"((cc)[0]), "+f"((cc)[1]), "+f"((cc)[2]), "+f"((cc)[3]) \
                 : "r"((a)[0]), "r"((a)[1]), "r"((a)[2]), "r"((a)[3]),        \
                   "r"(bb0), "r"(bb1))

#define CP_A16(dst, src, sz)                                                  \
    asm volatile("cp.async.cg.shared.global [%0], [%1], 16, %2;"              \
                 :: "r"(dst), "l"(src), "r"(sz) : "memory")
#define CP_COMMIT() asm volatile("cp.async.commit_group;" ::: "memory")
#define CP_WAIT1()  asm volatile("cp.async.wait_group 1;" ::: "memory")
#define CP_WAIT0()  asm volatile("cp.async.wait_group 0;" ::: "memory")

__device__ __forceinline__ void split2(float x, float y,
                                       uint32_t& hi, uint32_t& lo) {
    __nv_bfloat16 hx = __float2bfloat16_rn(x);
    __nv_bfloat16 hy = __float2bfloat16_rn(y);
    __nv_bfloat16 lx = __float2bfloat16_rn(x - __bfloat162float(hx));
    __nv_bfloat16 ly = __float2bfloat16_rn(y - __bfloat162float(hy));
    hi = ((uint32_t)__bfloat16_as_ushort(hy) << 16) | __bfloat16_as_ushort(hx);
    lo = ((uint32_t)__bfloat16_as_ushort(ly) << 16) | __bfloat16_as_ushort(lx);
}

// ===================== bf16x3 mma.sync GEMM v4 (R12 exact) =================
#define APITCH   40
#define A_U16    (64 * APITCH)
#define W_U16G   (128 * APITCH)
#define STAGE_U16 (2 * A_U16 + 2 * W_U16G)
#define OFF_AH   0
#define OFF_AL   A_U16
#define OFF_WH   (2 * A_U16)
#define OFF_WL   (2 * A_U16 + W_U16G)
#define GM_SMEM  (3 * STAGE_U16 * 2)

__global__ __launch_bounds__(256, 2) void gemm_v4(
    const __nv_bfloat16* __restrict__ Ahp,
    const __nv_bfloat16* __restrict__ Alp,
    const __nv_bfloat16* __restrict__ Whp,
    const __nv_bfloat16* __restrict__ Wlp,
    const float* __restrict__ b1, const float* __restrict__ b2,
    float* __restrict__ C, int M, int N, int K, int shiftT)
{
    extern __shared__ __align__(16) uint16_t sm16[];

    const int tid  = threadIdx.x;
    const int lane = tid & 31;
    const int wid  = tid >> 5;
    const int wm   = (wid & 1) * 32;
    const int wn   = (wid >> 1) * 32;
    const int row0 = blockIdx.y * 64;
    const int col0 = blockIdx.x * 128;

    float c[2][4][4];
#pragma unroll
    for (int i = 0; i < 2; i++)
#pragma unroll
        for (int j = 0; j < 4; j++)
#pragma unroll
            for (int q = 0; q < 4; q++) c[i][j][q] = 0.0f;

    const int nch = K / 32;

    const int ar = tid >> 2;
    const int ac = (tid & 3) * 8;
    int grow = row0 + ar;
    int srow = grow, ssz = 16;
    if (shiftT) {
        if ((grow % shiftT) == 0) ssz = 0;
        else srow = grow - 1;
    }

    auto issue = [&](int i) {
        uint16_t* st = sm16 + (i % 3) * STAGE_U16;
        const uint32_t sb = smem_u32(st);
        const int k0 = i * 32;
        uint32_t da = sb + (uint32_t)((ar * APITCH + ac) * 2);
        CP_A16(da + OFF_AH * 2, (const void*)&Ahp[(size_t)srow * K + k0 + ac], ssz);
        CP_A16(da + OFF_AL * 2, (const void*)&Alp[(size_t)srow * K + k0 + ac], ssz);
#pragma unroll
        for (int q = 0; q < 4; q++) {
            int e  = q * 256 + tid;
            int pl = e >> 9;
            int rr = (e >> 2) & 127;
            int cc = (e & 3) * 8;
            const __nv_bfloat16* Wp = pl ? Wlp : Whp;
            uint32_t dw = sb + (uint32_t)((pl ? OFF_WL : OFF_WH) * 2)
                        + (uint32_t)((rr * APITCH + cc) * 2);
            CP_A16(dw, (const void*)&Wp[(size_t)(col0 + rr) * K + k0 + cc], 16);
        }
    };

    issue(0);
    CP_COMMIT();
    if (nch > 1) issue(1);
    CP_COMMIT();

    for (int i = 0; i < nch; i++) {
        CP_WAIT1();
        __syncthreads();
        const uint32_t base = smem_u32(sm16 + (i % 3) * STAGE_U16);
#pragma unroll
        for (int kh = 0; kh < 2; kh++) {
            uint32_t ah[2][4], al[2][4];
            const int arow = wm + (lane & 15);
            const int akk  = kh * 16 + (lane >> 4) * 8;
#pragma unroll
            for (int mt = 0; mt < 2; mt++) {
                uint32_t boff = (uint32_t)(((arow + mt * 16) * APITCH + akk) * 2);
                LDSM4(ah[mt], base + OFF_AH * 2 + boff);
                LDSM4(al[mt], base + OFF_AL * 2 + boff);
            }
            uint32_t bh[2][4], bl[2][4];
            const int brow = wn + (lane & 7) + ((lane >> 4) << 3);
            const int bkk  = kh * 16 + ((lane >> 3) & 1) * 8;
#pragma unroll
            for (int np = 0; np < 2; np++) {
                uint32_t boff = (uint32_t)(((brow + np * 16) * APITCH + bkk) * 2);
                LDSM4(bh[np], base + OFF_WH * 2 + boff);
                LDSM4(bl[np], base + OFF_WL * 2 + boff);
            }
#pragma unroll
            for (int mt = 0; mt < 2; mt++)
#pragma unroll
                for (int np = 0; np < 2; np++)
#pragma unroll
                    for (int h = 0; h < 2; h++) {
                        int nt = np * 2 + h;
                        MMA_BF16(c[mt][nt], ah[mt], bh[np][h * 2], bh[np][h * 2 + 1]);
                        MMA_BF16(c[mt][nt], ah[mt], bl[np][h * 2], bl[np][h * 2 + 1]);
                        MMA_BF16(c[mt][nt], al[mt], bh[np][h * 2], bh[np][h * 2 + 1]);
                    }
        }
        if (i + 2 < nch) issue(i + 2);
        CP_COMMIT();
    }

#pragma unroll
    for (int mt = 0; mt < 2; mt++) {
#pragma unroll
        for (int nt = 0; nt < 4; nt++) {
            int m = row0 + wm + mt * 16 + (lane >> 2);
            int n = col0 + wn + nt * 8 + (lane & 3) * 2;
            float bx = b1[n]     + (b2 ? b2[n]     : 0.f);
            float by = b1[n + 1] + (b2 ? b2[n + 1] : 0.f);
            float2 v0 = make_float2(c[mt][nt][0] + bx, c[mt][nt][1] + by);
            float2 v1 = make_float2(c[mt][nt][2] + bx, c[mt][nt][3] + by);
            *(float2*)&C[(size_t)m * N + n]       = v0;
            *(float2*)&C[(size_t)(m + 8) * N + n] = v1;
        }
    }
}

// ===================== tensor-core persistent LSTM scan (R12 exact) ========
// Counter+flag barrier (all-thread poll), aliased gate buffer GPITCH 18,
// cp.async h staging.
#define WPITCH 520
#define W_U16S (64 * WPITCH)
#define H_U16S (32 * WPITCH)
#define GPITCH 18
#define GQ     (4 * 32 * GPITCH)
#define SCAN_SMEM ((2 * W_U16S + 2 * H_U16S) * 2)

__global__ __launch_bounds__(512, 1) void lstm_scan(
    const float* __restrict__ pre,            // [B,T,4H]
    const float* __restrict__ Whh,            // [4H,H] fp32 (split once here)
    const __nv_bfloat16* __restrict__ h0h,    // initial hidden planes or null
    const __nv_bfloat16* __restrict__ h0l,
    long long h0s,
    const float* __restrict__ cinit,          // [B,H] initial cell or null
    __nv_bfloat16* __restrict__ ph,           // output hidden planes [B,T,H]
    __nv_bfloat16* __restrict__ pl,
    unsigned* __restrict__ bar)               // group g: counter g*64, flag g*64+32
{
    extern __shared__ __align__(16) uint16_t sm16[];
    uint16_t* wsh = sm16;
    uint16_t* wsl = wsh + W_U16S;
    uint16_t* hsh = wsl + W_U16S;
    uint16_t* hsl = hsh + H_U16S;
    float*    gsm = (float*)hsh;              // ALIASED over h region

    const int tid  = threadIdx.x;
    const int lane = tid & 31;
    const int wid  = tid >> 5;
    const int gate = wid & 3;
    const int kbase = (wid >> 2) * 128;
    const int grp  = blockIdx.x;
    const int bi0  = grp * 32;
    const int hc0  = blockIdx.y * 16;
    unsigned* ctr  = bar + grp * 64;
    unsigned* flag = ctr + 32;

    // ---- load + split Whh slice once ----
    for (int idx = tid * 4; idx < 64 * 512; idx += 512 * 4) {
        int r  = idx >> 9;
        int k  = idx & 511;
        int gt = r >> 4;
        int rr = r & 15;
        float4 v = *(const float4*)&Whh[((size_t)gt * HH + hc0 + rr) * HH + k];
        uint32_t h0w, l0w, h1w, l1w;
        split2(v.x, v.y, h0w, l0w);
        split2(v.z, v.w, h1w, l1w);
        *(uint2*)&wsh[r * WPITCH + k] = make_uint2(h0w, h1w);
        *(uint2*)&wsl[r * WPITCH + k] = make_uint2(l0w, l1w);
    }

    const int j   = tid & 15;
    const int bl_ = tid >> 4;
    const int b_g = bi0 + bl_;
    const int col = hc0 + j;
    float c_r = cinit ? cinit[b_g * HH + col] : 0.0f;

    const uint32_t hshb = smem_u32(hsh);
    const uint32_t hslb = smem_u32(hsl);
    const uint32_t wshb = smem_u32(wsh);
    const uint32_t wslb = smem_u32(wsl);

    const int arow = lane & 15;
    const int aoff = (lane >> 4) * 8;
    const int brow = gate * 16 + (lane & 7) + ((lane >> 4) << 3);
    const int boff = ((lane >> 3) & 1) * 8;

    for (int t = 0; t < TT; t++) {
        // ---- prefetch pre(t) (h-independent; overlaps poll) ----
        float pr[4];
        {
            size_t prow = ((size_t)b_g * TT + t) * (size_t)G4;
#pragma unroll
            for (int g = 0; g < 4; g++)
                pr[g] = pre[prow + g * HH + col];
        }

        // ---- wait on read-only flag (all threads; R12 best config) ----
        if (t > 0) {
            unsigned v;
            do {
                asm volatile("ld.acquire.gpu.global.u32 %0, [%1];"
                             : "=r"(v) : "l"(flag) : "memory");
            } while (v < (unsigned)t);
        }

        // ---- stage h(t-1) via cp.async (global -> smem) ----
#pragma unroll
        for (int p = 0; p < 4; p++) {
            int e  = p * 512 + tid;
            int r  = e >> 6;
            int c8 = (e & 63) * 8;
            uint32_t d = (uint32_t)((r * WPITCH + c8) * 2);
            if (t == 0) {
                if (h0h) {
                    CP_A16(hshb + d, (const void*)&h0h[(size_t)(bi0 + r) * h0s + c8], 16);
                    CP_A16(hslb + d, (const void*)&h0l[(size_t)(bi0 + r) * h0s + c8], 16);
                } else {
                    CP_A16(hshb + d, (const void*)ph, 0);
                    CP_A16(hslb + d, (const void*)pl, 0);
                }
            } else {
                size_t off = ((size_t)(bi0 + r) * TT + (t - 1)) * HH + c8;
                CP_A16(hshb + d, (const void*)&ph[off], 16);
                CP_A16(hslb + d, (const void*)&pl[off], 16);
            }
        }
        CP_COMMIT();
        CP_WAIT0();
        __syncthreads();

        // ---- mma: this warp's gate over its K quarter ----
        float c[2][2][4];
#pragma unroll
        for (int mt = 0; mt < 2; mt++)
#pragma unroll
            for (int nt = 0; nt < 2; nt++)
#pragma unroll
                for (int q = 0; q < 4; q++) c[mt][nt][q] = 0.0f;

#pragma unroll
        for (int q = 0; q < 8; q++) {
            int kc = kbase + q * 16;
            uint32_t ah[2][4], al[2][4], bh4[4], bl4[4];
#pragma unroll
            for (int mt = 0; mt < 2; mt++) {
                uint32_t off = (uint32_t)(((mt * 16 + arow) * WPITCH + kc + aoff) * 2);
                LDSM4(ah[mt], hshb + off);
                LDSM4(al[mt], hslb + off);
            }
            {
                uint32_t off = (uint32_t)((brow * WPITCH + kc + boff) * 2);
                LDSM4(bh4, wshb + off);
                LDSM4(bl4, wslb + off);
            }
#pragma unroll
            for (int mt = 0; mt < 2; mt++)
#pragma unroll
                for (int h = 0; h < 2; h++) {
                    MMA_BF16(c[mt][h], ah[mt], bh4[h * 2], bh4[h * 2 + 1]);
                    MMA_BF16(c[mt][h], ah[mt], bl4[h * 2], bl4[h * 2 + 1]);
                    MMA_BF16(c[mt][h], al[mt], bh4[h * 2], bh4[h * 2 + 1]);
                }
        }
        __syncthreads();   // all mma reads of h done before gsm overwrite

        // ---- fragments -> aliased gate buffer (own quarter section) ----
        float* gq = gsm + (wid >> 2) * GQ;
#pragma unroll
        for (int mt = 0; mt < 2; mt++)
#pragma unroll
            for (int nt = 0; nt < 2; nt++) {
                int m = mt * 16 + (lane >> 2);
                int n = nt * 8 + (lane & 3) * 2;
                float* gbase = gq + (gate * 32 + m) * GPITCH + n;
                *(float2*)gbase                = make_float2(c[mt][nt][0], c[mt][nt][1]);
                *(float2*)(gbase + 8 * GPITCH) = make_float2(c[mt][nt][2], c[mt][nt][3]);
            }
        __syncthreads();

        // ---- gates + state update: one (b, col) per thread ----
        {
            float gv[4];
#pragma unroll
            for (int g = 0; g < 4; g++) {
                float s = pr[g];
#pragma unroll
                for (int q = 0; q < 4; q++)
                    s += gsm[q * GQ + (g * 32 + bl_) * GPITCH + j];
                gv[g] = s;
            }
            float i_ = 1.0f / (1.0f + __expf(-gv[0]));
            float f_ = 1.0f / (1.0f + __expf(-gv[1]));
            float e2 = __expf(2.0f * gv[2]);
            float g_ = (e2 - 1.0f) / (e2 + 1.0f);
            float o_ = 1.0f / (1.0f + __expf(-gv[3]));

            float cn = f_ * c_r + i_ * g_;
            c_r = cn;
            float ec = __expf(2.0f * cn);
            float th = (ec - 1.0f) / (ec + 1.0f);
            float hv = o_ * th;

            __nv_bfloat16 hh = __float2bfloat16_rn(hv);
            __nv_bfloat16 hl = __float2bfloat16_rn(hv - __bfloat162float(hh));
            size_t off = ((size_t)b_g * TT + t) * HH + col;
            ph[off] = hh;
            pl[off] = hl;
        }

        // ---- arrive: counter RMW; last arriver release-stores the flag ----
        __syncthreads();
        if (tid == 0) {
            unsigned old;
            asm volatile("atom.acq_rel.gpu.global.add.u32 %0, [%1], %2;"
                         : "=r"(old) : "l"(ctr), "r"(1u) : "memory");
            if (old == (unsigned)(t * 32 + 31)) {
                asm volatile("st.release.gpu.global.u32 [%0], %1;"
                             :: "l"(flag), "r"((unsigned)(t + 1)) : "memory");
            }
        }
    }
}

// ---------------- host driver --------------------------------------------
extern "C" void kernel_launch(void* const* d_in, const int* in_sizes, int n_in,
                              void* d_out, int out_size)
{
    const float* x     = (const float*)d_in[0];
    const float* c_dec = (const float*)d_in[1];
    const float* eWih0 = (const float*)d_in[2];
    const float* eWhh0 = (const float*)d_in[3];
    const float* ebih0 = (const float*)d_in[4];
    const float* ebhh0 = (const float*)d_in[5];
    const float* eWih1 = (const float*)d_in[6];
    const float* eWhh1 = (const float*)d_in[7];
    const float* ebih1 = (const float*)d_in[8];
    const float* ebhh1 = (const float*)d_in[9];
    const float* dWih0 = (const float*)d_in[10];
    const float* dWhh0 = (const float*)d_in[11];
    const float* dbih0 = (const float*)d_in[12];
    const float* dbhh0 = (const float*)d_in[13];
    const float* dWih1 = (const float*)d_in[14];
    const float* dWhh1 = (const float*)d_in[15];
    const float* dbih1 = (const float*)d_in[16];
    const float* dbhh1 = (const float*)d_in[17];
    const float* fcW   = (const float*)d_in[18];
    const float* fcB   = (const float*)d_in[19];
    float*       out   = (float*)d_out;

    static float *pre = nullptr, *pre2 = nullptr;
    static __nv_bfloat16 *bXh, *bXl, *bYh, *bYl, *xh, *xl, *wh, *wl;
    static unsigned *bars = nullptr;
    static cudaStream_t side = nullptr;
    static cudaEvent_t evFork = nullptr, evJoin = nullptr;
    static bool inited = false;
    if (!inited) {
        cudaGetSymbolAddress((void**)&pre,  g_pre);
        cudaGetSymbolAddress((void**)&pre2, g_pre2);
        cudaGetSymbolAddress((void**)&bXh,  g_bufXh);
        cudaGetSymbolAddress((void**)&bXl,  g_bufXl);
        cudaGetSymbolAddress((void**)&bYh,  g_bufYh);
        cudaGetSymbolAddress((void**)&bYl,  g_bufYl);
        cudaGetSymbolAddress((void**)&xh,   g_xh);
        cudaGetSymbolAddress((void**)&xl,   g_xl);
        cudaGetSymbolAddress((void**)&wh,   g_wh);
        cudaGetSymbolAddress((void**)&wl,   g_wl);
        cudaGetSymbolAddress((void**)&bars, g_barrier);
        cudaFuncSetAttribute(lstm_scan,
                             cudaFuncAttributeMaxDynamicSharedMemorySize, SCAN_SMEM);
        cudaFuncSetAttribute(gemm_v4,
                             cudaFuncAttributeMaxDynamicSharedMemorySize, GM_SMEM);
        cudaStreamCreateWithFlags(&side, cudaStreamNonBlocking);
        cudaEventCreateWithFlags(&evFork, cudaEventDisableTiming);
        cudaEventCreateWithFlags(&evJoin, cudaEventDisableTiming);
        // warm the side stream's internal resources before any graph capture
        zero_bar<<<1, 32, 0, side>>>(bars, 0);
        cudaStreamSynchronize(side);
        inited = true;
    }

    const int M = BB * TT;
    const dim3 gemmGrid2048(G4 / 128, M / 64);
    const dim3 gemmGrid128(II / 128,  M / 64);
    const dim3 scanGrid(4, 32);
    const long long seqStride = (long long)TT * HH;

    zero_bar<<<4, 256>>>(bars, 1024);

    // ---- pre-split x and all feed-forward weights into bf16 planes ----
    split_planes<<<(M * II + 255) / 256, 256>>>(x, xh, xl, M * II);
    split_planes<<<(2048 * 128 + 255) / 256, 256>>>(eWih0, wh + WO0, wl + WO0, 2048 * 128);
    split_planes<<<(2048 * 512 + 255) / 256, 256>>>(eWih1, wh + WO1, wl + WO1, 2048 * 512);
    split_planes<<<(2048 * 128 + 255) / 256, 256>>>(dWih0, wh + WO2, wl + WO2, 2048 * 128);
    split_planes<<<(2048 * 512 + 255) / 256, 256>>>(dWih1, wh + WO3, wl + WO3, 2048 * 512);
    split_planes<<<(128 * 512 + 255) / 256, 256>>>(fcW,   wh + WO4, wl + WO4, 128 * 512);

    // ---- fork: dec0 projection (depends only on x planes) on side stream ----
    cudaEventRecord(evFork, 0);
    cudaStreamWaitEvent(side, evFork, 0);
    gemm_v4<<<gemmGrid2048, 256, GM_SMEM, side>>>(
        xh, xl, wh + WO2, wl + WO2, dbih0, dbhh0, pre2, M, G4, II, TT);
    cudaEventRecord(evJoin, side);

    // ---- encoder layer 0 (A = x planes) ----
    gemm_v4<<<gemmGrid2048, 256, GM_SMEM>>>(
        xh, xl, wh + WO0, wl + WO0, ebih0, ebhh0, pre, M, G4, II, 0);
    lstm_scan<<<scanGrid, 512, SCAN_SMEM>>>(pre, eWhh0, nullptr, nullptr, 0, nullptr,
                                            bXh, bXl, bars + 0 * 256);

    // ---- encoder layer 1 (A = bufX planes) ----
    gemm_v4<<<gemmGrid2048, 256, GM_SMEM>>>(
        bXh, bXl, wh + WO1, wl + WO1, ebih1, ebhh1, pre, M, G4, HH, 0);
    lstm_scan<<<scanGrid, 512, SCAN_SMEM>>>(pre, eWhh1, nullptr, nullptr, 0, nullptr,
                                            bYh, bYl, bars + 1 * 256);

    // ---- join: dec0 scan consumes the overlapped projection ----
    cudaStreamWaitEvent(0, evJoin, 0);
    lstm_scan<<<scanGrid, 512, SCAN_SMEM>>>(pre2, dWhh0,
                                            bXh + (size_t)(TT - 1) * HH,
                                            bXl + (size_t)(TT - 1) * HH,
                                            seqStride, c_dec,
                                            bXh, bXl, bars + 2 * 256);

    // ---- decoder layer 1 (A = bufX planes; h0 = enc1 final row) ----
    gemm_v4<<<gemmGrid2048, 256, GM_SMEM>>>(
        bXh, bXl, wh + WO3, wl + WO3, dbih1, dbhh1, pre, M, G4, HH, 0);
    lstm_scan<<<scanGrid, 512, SCAN_SMEM>>>(pre, dWhh1,
                                            bYh + (size_t)(TT - 1) * HH,
                                            bYl + (size_t)(TT - 1) * HH,
                                            seqStride, c_dec + BB * HH,
                                            bYh, bYl, bars + 3 * 256);

    // ---- FC head (A = bufY planes) ----
    gemm_v4<<<gemmGrid128, 256, GM_SMEM>>>(
        bYh, bYl, wh + WO4, wl + WO4, fcB, nullptr, out, M, II, HH, 0);
}

// round 17
// speedup vs baseline: 1.1643x; 1.0115x over previous
#include <cuda_runtime.h>
#include <cuda_bf16.h>
#include <math.h>
#include <stdint.h>

// Problem constants
#define BB   128      // batch
#define TT   512      // time steps
#define HH   512      // hidden
#define II   128      // input dim
#define G4   2048     // 4*H

// ---------------- scratch (static device memory; no allocations) ----------
__device__ float g_pre [(size_t)BB * TT * G4];
__device__ __align__(16) __nv_bfloat16 g_bufXh[(size_t)BB * TT * HH];
__device__ __align__(16) __nv_bfloat16 g_bufXl[(size_t)BB * TT * HH];
__device__ __align__(16) __nv_bfloat16 g_bufYh[(size_t)BB * TT * HH];
__device__ __align__(16) __nv_bfloat16 g_bufYl[(size_t)BB * TT * HH];
__device__ __align__(16) __nv_bfloat16 g_xh[(size_t)BB * TT * II];
__device__ __align__(16) __nv_bfloat16 g_xl[(size_t)BB * TT * II];
// weight planes: [enc0 2048x128][enc1 2048x512][dec0 2048x128][dec1 2048x512][fc 128x512]
#define WO0 0
#define WO1 (WO0 + 2048 * 128)
#define WO2 (WO1 + 2048 * 512)
#define WO3 (WO2 + 2048 * 128)
#define WO4 (WO3 + 2048 * 512)
#define WTOT (WO4 + 128 * 512)
__device__ __align__(16) __nv_bfloat16 g_wh[WTOT];
__device__ __align__(16) __nv_bfloat16 g_wl[WTOT];
__device__ unsigned g_barrier[1024];  // 4 layers x 4 groups: counter g*64, flag g*64+32

// ---------------- tiny init kernels ----------------------------------------
__global__ void zero_bar(unsigned* p, int n) {
    int i = blockIdx.x * blockDim.x + threadIdx.x;
    if (i < n) p[i] = 0u;
}
__global__ void split_planes(const float* __restrict__ in,
                             __nv_bfloat16* __restrict__ oh,
                             __nv_bfloat16* __restrict__ ol, int n) {
    int i = blockIdx.x * blockDim.x + threadIdx.x;
    if (i < n) {
        float v = in[i];
        __nv_bfloat16 h = __float2bfloat16_rn(v);
        oh[i] = h;
        ol[i] = __float2bfloat16_rn(v - __bfloat162float(h));
    }
}

// ======================= helpers (compute_103-safe) ========================
__device__ __forceinline__ uint32_t smem_u32(const void* p) {
    return (uint32_t)__cvta_generic_to_shared(p);
}

#define LDSM4(d, addr)                                                        \
    asm volatile("ldmatrix.sync.aligned.m8n8.x4.shared.b16 "                  \
                 "{%0,%1,%2,%3}, [%4];"                                       \
                 : "=r"((d)[0]), "=r"((d)[1]), "=r"((d)[2]), "=r"((d)[3])     \
                 : "r"(addr))

#define MMA_BF16(cc, a, bb0, bb1)                                             \
    asm volatile("mma.sync.aligned.m16n8k16.row.col.f32.bf16.bf16.f32 "       \
                 "{%0,%1,%2,%3}, {%4,%5,%6,%7}, {%8,%9}, {%0,%1,%2,%3};"      \
                 : "+f"((cc)[0]), "+f"((cc)[1]), "+f"((cc)[2]), "+f"((cc)[3]) \
                 : "r"((a)[0]), "r"((a)[1]), "r"((a)[2]), "r"((a)[3]),        \
                   "r"(bb0), "r"(bb1))

#define CP_A16(dst, src, sz)                                                  \
    asm volatile("cp.async.cg.shared.global [%0], [%1], 16, %2;"              \
                 :: "r"(dst), "l"(src), "r"(sz) : "memory")
#define CP_COMMIT() asm volatile("cp.async.commit_group;" ::: "memory")
#define CP_WAIT1()  asm volatile("cp.async.wait_group 1;" ::: "memory")
#define CP_WAIT0()  asm volatile("cp.async.wait_group 0;" ::: "memory")
#define BAR_SYNC(id, cnt) \
    asm volatile("bar.sync %0, %1;" :: "r"(id), "r"(cnt) : "memory")

__device__ __forceinline__ void split2(float x, float y,
                                       uint32_t& hi, uint32_t& lo) {
    __nv_bfloat16 hx = __float2bfloat16_rn(x);
    __nv_bfloat16 hy = __float2bfloat16_rn(y);
    __nv_bfloat16 lx = __float2bfloat16_rn(x - __bfloat162float(hx));
    __nv_bfloat16 ly = __float2bfloat16_rn(y - __bfloat162float(hy));
    hi = ((uint32_t)__bfloat16_as_ushort(hy) << 16) | __bfloat16_as_ushort(hx);
    lo = ((uint32_t)__bfloat16_as_ushort(ly) << 16) | __bfloat16_as_ushort(lx);
}

// ===================== bf16x3 mma.sync GEMM v4 (R12 exact) =================
#define APITCH   40
#define A_U16    (64 * APITCH)
#define W_U16G   (128 * APITCH)
#define STAGE_U16 (2 * A_U16 + 2 * W_U16G)
#define OFF_AH   0
#define OFF_AL   A_U16
#define OFF_WH   (2 * A_U16)
#define OFF_WL   (2 * A_U16 + W_U16G)
#define GM_SMEM  (3 * STAGE_U16 * 2)

__global__ __launch_bounds__(256, 2) void gemm_v4(
    const __nv_bfloat16* __restrict__ Ahp,
    const __nv_bfloat16* __restrict__ Alp,
    const __nv_bfloat16* __restrict__ Whp,
    const __nv_bfloat16* __restrict__ Wlp,
    const float* __restrict__ b1, const float* __restrict__ b2,
    float* __restrict__ C, int M, int N, int K, int shiftT)
{
    extern __shared__ __align__(16) uint16_t sm16[];

    const int tid  = threadIdx.x;
    const int lane = tid & 31;
    const int wid  = tid >> 5;
    const int wm   = (wid & 1) * 32;
    const int wn   = (wid >> 1) * 32;
    const int row0 = blockIdx.y * 64;
    const int col0 = blockIdx.x * 128;

    float c[2][4][4];
#pragma unroll
    for (int i = 0; i < 2; i++)
#pragma unroll
        for (int j = 0; j < 4; j++)
#pragma unroll
            for (int q = 0; q < 4; q++) c[i][j][q] = 0.0f;

    const int nch = K / 32;

    const int ar = tid >> 2;
    const int ac = (tid & 3) * 8;
    int grow = row0 + ar;
    int srow = grow, ssz = 16;
    if (shiftT) {
        if ((grow % shiftT) == 0) ssz = 0;
        else srow = grow - 1;
    }

    auto issue = [&](int i) {
        uint16_t* st = sm16 + (i % 3) * STAGE_U16;
        const uint32_t sb = smem_u32(st);
        const int k0 = i * 32;
        uint32_t da = sb + (uint32_t)((ar * APITCH + ac) * 2);
        CP_A16(da + OFF_AH * 2, (const void*)&Ahp[(size_t)srow * K + k0 + ac], ssz);
        CP_A16(da + OFF_AL * 2, (const void*)&Alp[(size_t)srow * K + k0 + ac], ssz);
#pragma unroll
        for (int q = 0; q < 4; q++) {
            int e  = q * 256 + tid;
            int pl = e >> 9;
            int rr = (e >> 2) & 127;
            int cc = (e & 3) * 8;
            const __nv_bfloat16* Wp = pl ? Wlp : Whp;
            uint32_t dw = sb + (uint32_t)((pl ? OFF_WL : OFF_WH) * 2)
                        + (uint32_t)((rr * APITCH + cc) * 2);
            CP_A16(dw, (const void*)&Wp[(size_t)(col0 + rr) * K + k0 + cc], 16);
        }
    };

    issue(0);
    CP_COMMIT();
    if (nch > 1) issue(1);
    CP_COMMIT();

    for (int i = 0; i < nch; i++) {
        CP_WAIT1();
        __syncthreads();
        const uint32_t base = smem_u32(sm16 + (i % 3) * STAGE_U16);
#pragma unroll
        for (int kh = 0; kh < 2; kh++) {
            uint32_t ah[2][4], al[2][4];
            const int arow = wm + (lane & 15);
            const int akk  = kh * 16 + (lane >> 4) * 8;
#pragma unroll
            for (int mt = 0; mt < 2; mt++) {
                uint32_t boff = (uint32_t)(((arow + mt * 16) * APITCH + akk) * 2);
                LDSM4(ah[mt], base + OFF_AH * 2 + boff);
                LDSM4(al[mt], base + OFF_AL * 2 + boff);
            }
            uint32_t bh[2][4], bl[2][4];
            const int brow = wn + (lane & 7) + ((lane >> 4) << 3);
            const int bkk  = kh * 16 + ((lane >> 3) & 1) * 8;
#pragma unroll
            for (int np = 0; np < 2; np++) {
                uint32_t boff = (uint32_t)(((brow + np * 16) * APITCH + bkk) * 2);
                LDSM4(bh[np], base + OFF_WH * 2 + boff);
                LDSM4(bl[np], base + OFF_WL * 2 + boff);
            }
#pragma unroll
            for (int mt = 0; mt < 2; mt++)
#pragma unroll
                for (int np = 0; np < 2; np++)
#pragma unroll
                    for (int h = 0; h < 2; h++) {
                        int nt = np * 2 + h;
                        MMA_BF16(c[mt][nt], ah[mt], bh[np][h * 2], bh[np][h * 2 + 1]);
                        MMA_BF16(c[mt][nt], ah[mt], bl[np][h * 2], bl[np][h * 2 + 1]);
                        MMA_BF16(c[mt][nt], al[mt], bh[np][h * 2], bh[np][h * 2 + 1]);
                    }
        }
        if (i + 2 < nch) issue(i + 2);
        CP_COMMIT();
    }

#pragma unroll
    for (int mt = 0; mt < 2; mt++) {
#pragma unroll
        for (int nt = 0; nt < 4; nt++) {
            int m = row0 + wm + mt * 16 + (lane >> 2);
            int n = col0 + wn + nt * 8 + (lane & 3) * 2;
            float bx = b1[n]     + (b2 ? b2[n]     : 0.f);
            float by = b1[n + 1] + (b2 ? b2[n + 1] : 0.f);
            float2 v0 = make_float2(c[mt][nt][0] + bx, c[mt][nt][1] + by);
            float2 v1 = make_float2(c[mt][nt][2] + bx, c[mt][nt][3] + by);
            *(float2*)&C[(size_t)m * N + n]       = v0;
            *(float2*)&C[(size_t)(m + 8) * N + n] = v1;
        }
    }
}

// ===================== tensor-core persistent LSTM scan v12 ================
// R12 exact EXCEPT h staging: each K-quarter's 4 warps (contiguous 128
// threads) load ONLY their own quarter via cp.async, wait_group 0, and sync
// among themselves with a named barrier. Quarter 0's mma starts after a
// 16.6KB load instead of waiting for the full 66.5KB. The aliased gate
// buffer still uses the existing full __syncthreads after mma (unchanged).
#define WPITCH 520
#define W_U16S (64 * WPITCH)
#define H_U16S (32 * WPITCH)
#define GPITCH 18
#define GQ     (4 * 32 * GPITCH)
#define SCAN_SMEM ((2 * W_U16S + 2 * H_U16S) * 2)

__global__ __launch_bounds__(512, 1) void lstm_scan(
    const float* __restrict__ pre,            // [B,T,4H]
    const float* __restrict__ Whh,            // [4H,H] fp32 (split once here)
    const __nv_bfloat16* __restrict__ h0h,    // initial hidden planes or null
    const __nv_bfloat16* __restrict__ h0l,
    long long h0s,
    const float* __restrict__ cinit,          // [B,H] initial cell or null
    __nv_bfloat16* __restrict__ ph,           // output hidden planes [B,T,H]
    __nv_bfloat16* __restrict__ pl,
    unsigned* __restrict__ bar)               // group g: counter g*64, flag g*64+32
{
    extern __shared__ __align__(16) uint16_t sm16[];
    uint16_t* wsh = sm16;
    uint16_t* wsl = wsh + W_U16S;
    uint16_t* hsh = wsl + W_U16S;
    uint16_t* hsl = hsh + H_U16S;
    float*    gsm = (float*)hsh;              // ALIASED over h region

    const int tid  = threadIdx.x;
    const int lane = tid & 31;
    const int wid  = tid >> 5;
    const int gate = wid & 3;
    const int kq   = wid >> 2;                // K quarter 0..3
    const int kbase = kq * 128;
    const int grp  = blockIdx.x;
    const int bi0  = grp * 32;
    const int hc0  = blockIdx.y * 16;
    unsigned* ctr  = bar + grp * 64;
    unsigned* flag = ctr + 32;

    // ---- load + split Whh slice once ----
    for (int idx = tid * 4; idx < 64 * 512; idx += 512 * 4) {
        int r  = idx >> 9;
        int k  = idx & 511;
        int gt = r >> 4;
        int rr = r & 15;
        float4 v = *(const float4*)&Whh[((size_t)gt * HH + hc0 + rr) * HH + k];
        uint32_t h0w, l0w, h1w, l1w;
        split2(v.x, v.y, h0w, l0w);
        split2(v.z, v.w, h1w, l1w);
        *(uint2*)&wsh[r * WPITCH + k] = make_uint2(h0w, h1w);
        *(uint2*)&wsl[r * WPITCH + k] = make_uint2(l0w, l1w);
    }

    const int j   = tid & 15;
    const int bl_ = tid >> 4;
    const int b_g = bi0 + bl_;
    const int col = hc0 + j;
    float c_r = cinit ? cinit[b_g * HH + col] : 0.0f;

    const uint32_t hshb = smem_u32(hsh);
    const uint32_t hslb = smem_u32(hsl);
    const uint32_t wshb = smem_u32(wsh);
    const uint32_t wslb = smem_u32(wsl);

    const int arow = lane & 15;
    const int aoff = (lane >> 4) * 8;
    const int brow = gate * 16 + (lane & 7) + ((lane >> 4) << 3);
    const int boff = ((lane >> 3) & 1) * 8;

    // quarter-staging map: group thread gtid (0..127) covers 32 rows x 16
    // col-groups (own 128 k-cols): 4 slots, r = s*8 + (gtid>>4),
    // c8 = (kq*16 + (gtid&15)) * 8
    const int gtid = tid & 127;
    const int srow4 = gtid >> 4;
    const int scg   = (kq * 16 + (gtid & 15)) * 8;

    for (int t = 0; t < TT; t++) {
        // ---- prefetch pre(t) (h-independent; overlaps poll) ----
        float pr[4];
        {
            size_t prow = ((size_t)b_g * TT + t) * (size_t)G4;
#pragma unroll
            for (int g = 0; g < 4; g++)
                pr[g] = pre[prow + g * HH + col];
        }

        // ---- wait on read-only flag (all threads; R12 best config) ----
        if (t > 0) {
            unsigned v;
            do {
                asm volatile("ld.acquire.gpu.global.u32 %0, [%1];"
                             : "=r"(v) : "l"(flag) : "memory");
            } while (v < (unsigned)t);
        }

        // ---- stage OWN K-quarter of h(t-1) via cp.async ----
#pragma unroll
        for (int s = 0; s < 4; s++) {
            int r  = s * 8 + srow4;
            uint32_t d = (uint32_t)((r * WPITCH + scg) * 2);
            if (t == 0) {
                if (h0h) {
                    CP_A16(hshb + d, (const void*)&h0h[(size_t)(bi0 + r) * h0s + scg], 16);
                    CP_A16(hslb + d, (const void*)&h0l[(size_t)(bi0 + r) * h0s + scg], 16);
                } else {
                    CP_A16(hshb + d, (const void*)ph, 0);
                    CP_A16(hslb + d, (const void*)pl, 0);
                }
            } else {
                size_t off = ((size_t)(bi0 + r) * TT + (t - 1)) * HH + scg;
                CP_A16(hshb + d, (const void*)&ph[off], 16);
                CP_A16(hslb + d, (const void*)&pl[off], 16);
            }
        }
        CP_COMMIT();
        CP_WAIT0();
        BAR_SYNC(1 + kq, 128);   // own quarter's 4 warps: h quarter visible

        // ---- mma: this warp's gate over its K quarter ----
        float c[2][2][4];
#pragma unroll
        for (int mt = 0; mt < 2; mt++)
#pragma unroll
            for (int nt = 0; nt < 2; nt++)
#pragma unroll
                for (int q = 0; q < 4; q++) c[mt][nt][q] = 0.0f;

#pragma unroll
        for (int q = 0; q < 8; q++) {
            int kc = kbase + q * 16;
            uint32_t ah[2][4], al[2][4], bh4[4], bl4[4];
#pragma unroll
            for (int mt = 0; mt < 2; mt++) {
                uint32_t off = (uint32_t)(((mt * 16 + arow) * WPITCH + kc + aoff) * 2);
                LDSM4(ah[mt], hshb + off);
                LDSM4(al[mt], hslb + off);
            }
            {
                uint32_t off = (uint32_t)((brow * WPITCH + kc + boff) * 2);
                LDSM4(bh4, wshb + off);
                LDSM4(bl4, wslb + off);
            }
#pragma unroll
            for (int mt = 0; mt < 2; mt++)
#pragma unroll
                for (int h = 0; h < 2; h++) {
                    MMA_BF16(c[mt][h], ah[mt], bh4[h * 2], bh4[h * 2 + 1]);
                    MMA_BF16(c[mt][h], ah[mt], bl4[h * 2], bl4[h * 2 + 1]);
                    MMA_BF16(c[mt][h], al[mt], bh4[h * 2], bh4[h * 2 + 1]);
                }
        }
        __syncthreads();   // all mma reads of h done before gsm overwrite

        // ---- fragments -> aliased gate buffer (own quarter section) ----
        float* gq = gsm + kq * GQ;
#pragma unroll
        for (int mt = 0; mt < 2; mt++)
#pragma unroll
            for (int nt = 0; nt < 2; nt++) {
                int m = mt * 16 + (lane >> 2);
                int n = nt * 8 + (lane & 3) * 2;
                float* gbase = gq + (gate * 32 + m) * GPITCH + n;
                *(float2*)gbase                = make_float2(c[mt][nt][0], c[mt][nt][1]);
                *(float2*)(gbase + 8 * GPITCH) = make_float2(c[mt][nt][2], c[mt][nt][3]);
            }
        __syncthreads();

        // ---- gates + state update: one (b, col) per thread ----
        {
            float gv[4];
#pragma unroll
            for (int g = 0; g < 4; g++) {
                float s = pr[g];
#pragma unroll
                for (int q = 0; q < 4; q++)
                    s += gsm[q * GQ + (g * 32 + bl_) * GPITCH + j];
                gv[g] = s;
            }
            float i_ = 1.0f / (1.0f + __expf(-gv[0]));
            float f_ = 1.0f / (1.0f + __expf(-gv[1]));
            float e2 = __expf(2.0f * gv[2]);
            float g_ = (e2 - 1.0f) / (e2 + 1.0f);
            float o_ = 1.0f / (1.0f + __expf(-gv[3]));

            float cn = f_ * c_r + i_ * g_;
            c_r = cn;
            float ec = __expf(2.0f * cn);
            float th = (ec - 1.0f) / (ec + 1.0f);
            float hv = o_ * th;

            __nv_bfloat16 hh = __float2bfloat16_rn(hv);
            __nv_bfloat16 hl = __float2bfloat16_rn(hv - __bfloat162float(hh));
            size_t off = ((size_t)b_g * TT + t) * HH + col;
            ph[off] = hh;
            pl[off] = hl;
        }

        // ---- arrive: counter RMW; last arriver release-stores the flag ----
        __syncthreads();
        if (tid == 0) {
            unsigned old;
            asm volatile("atom.acq_rel.gpu.global.add.u32 %0, [%1], %2;"
                         : "=r"(old) : "l"(ctr), "r"(1u) : "memory");
            if (old == (unsigned)(t * 32 + 31)) {
                asm volatile("st.release.gpu.global.u32 [%0], %1;"
                             :: "l"(flag), "r"((unsigned)(t + 1)) : "memory");
            }
        }
    }
}

// ---------------- host driver (R12 exact) ----------------------------------
extern "C" void kernel_launch(void* const* d_in, const int* in_sizes, int n_in,
                              void* d_out, int out_size)
{
    const float* x     = (const float*)d_in[0];
    const float* c_dec = (const float*)d_in[1];
    const float* eWih0 = (const float*)d_in[2];
    const float* eWhh0 = (const float*)d_in[3];
    const float* ebih0 = (const float*)d_in[4];
    const float* ebhh0 = (const float*)d_in[5];
    const float* eWih1 = (const float*)d_in[6];
    const float* eWhh1 = (const float*)d_in[7];
    const float* ebih1 = (const float*)d_in[8];
    const float* ebhh1 = (const float*)d_in[9];
    const float* dWih0 = (const float*)d_in[10];
    const float* dWhh0 = (const float*)d_in[11];
    const float* dbih0 = (const float*)d_in[12];
    const float* dbhh0 = (const float*)d_in[13];
    const float* dWih1 = (const float*)d_in[14];
    const float* dWhh1 = (const float*)d_in[15];
    const float* dbih1 = (const float*)d_in[16];
    const float* dbhh1 = (const float*)d_in[17];
    const float* fcW   = (const float*)d_in[18];
    const float* fcB   = (const float*)d_in[19];
    float*       out   = (float*)d_out;

    static float *pre = nullptr;
    static __nv_bfloat16 *bXh, *bXl, *bYh, *bYl, *xh, *xl, *wh, *wl;
    static unsigned *bars = nullptr;
    static bool inited = false;
    if (!inited) {
        cudaGetSymbolAddress((void**)&pre,  g_pre);
        cudaGetSymbolAddress((void**)&bXh,  g_bufXh);
        cudaGetSymbolAddress((void**)&bXl,  g_bufXl);
        cudaGetSymbolAddress((void**)&bYh,  g_bufYh);
        cudaGetSymbolAddress((void**)&bYl,  g_bufYl);
        cudaGetSymbolAddress((void**)&xh,   g_xh);
        cudaGetSymbolAddress((void**)&xl,   g_xl);
        cudaGetSymbolAddress((void**)&wh,   g_wh);
        cudaGetSymbolAddress((void**)&wl,   g_wl);
        cudaGetSymbolAddress((void**)&bars, g_barrier);
        cudaFuncSetAttribute(lstm_scan,
                             cudaFuncAttributeMaxDynamicSharedMemorySize, SCAN_SMEM);
        cudaFuncSetAttribute(gemm_v4,
                             cudaFuncAttributeMaxDynamicSharedMemorySize, GM_SMEM);
        inited = true;
    }

    const int M = BB * TT;
    const dim3 gemmGrid2048(G4 / 128, M / 64);
    const dim3 gemmGrid128(II / 128,  M / 64);
    const dim3 scanGrid(4, 32);
    const long long seqStride = (long long)TT * HH;

    zero_bar<<<4, 256>>>(bars, 1024);

    // ---- pre-split x and all feed-forward weights into bf16 planes ----
    split_planes<<<(M * II + 255) / 256, 256>>>(x, xh, xl, M * II);
    split_planes<<<(2048 * 128 + 255) / 256, 256>>>(eWih0, wh + WO0, wl + WO0, 2048 * 128);
    split_planes<<<(2048 * 512 + 255) / 256, 256>>>(eWih1, wh + WO1, wl + WO1, 2048 * 512);
    split_planes<<<(2048 * 128 + 255) / 256, 256>>>(dWih0, wh + WO2, wl + WO2, 2048 * 128);
    split_planes<<<(2048 * 512 + 255) / 256, 256>>>(dWih1, wh + WO3, wl + WO3, 2048 * 512);
    split_planes<<<(128 * 512 + 255) / 256, 256>>>(fcW,   wh + WO4, wl + WO4, 128 * 512);

    // ---- encoder layer 0 (A = x planes) ----
    gemm_v4<<<gemmGrid2048, 256, GM_SMEM>>>(
        xh, xl, wh + WO0, wl + WO0, ebih0, ebhh0, pre, M, G4, II, 0);
    lstm_scan<<<scanGrid, 512, SCAN_SMEM>>>(pre, eWhh0, nullptr, nullptr, 0, nullptr,
                                            bXh, bXl, bars + 0 * 256);

    // ---- encoder layer 1 (A = bufX planes) ----
    gemm_v4<<<gemmGrid2048, 256, GM_SMEM>>>(
        bXh, bXl, wh + WO1, wl + WO1, ebih1, ebhh1, pre, M, G4, HH, 0);
    lstm_scan<<<scanGrid, 512, SCAN_SMEM>>>(pre, eWhh1, nullptr, nullptr, 0, nullptr,
                                            bYh, bYl, bars + 1 * 256);

    // ---- decoder layer 0 (A = x planes shifted; h0 = enc0 final row) ----
    gemm_v4<<<gemmGrid2048, 256, GM_SMEM>>>(
        xh, xl, wh + WO2, wl + WO2, dbih0, dbhh0, pre, M, G4, II, TT);
    lstm_scan<<<scanGrid, 512, SCAN_SMEM>>>(pre, dWhh0,
                                            bXh + (size_t)(TT - 1) * HH,
                                            bXl + (size_t)(TT - 1) * HH,
                                            seqStride, c_dec,
                                            bXh, bXl, bars + 2 * 256);

    // ---- decoder layer 1 (A = bufX planes; h0 = enc1 final row) ----
    gemm_v4<<<gemmGrid2048, 256, GM_SMEM>>>(
        bXh, bXl, wh + WO3, wl + WO3, dbih1, dbhh1, pre, M, G4, HH, 0);
    lstm_scan<<<scanGrid, 512, SCAN_SMEM>>>(pre, dWhh1,
                                            bYh + (size_t)(TT - 1) * HH,
                                            bYl + (size_t)(TT - 1) * HH,
                                            seqStride, c_dec + BB * HH,
                                            bYh, bYl, bars + 3 * 256);

    // ---- FC head (A = bufY planes) ----
    gemm_v4<<<gemmGrid128, 256, GM_SMEM>>>(
        bYh, bYl, wh + WO4, wl + WO4, fcB, nullptr, out, M, II, HH, 0);
}